// round 3
// baseline (speedup 1.0000x reference)
#include <cuda_runtime.h>

#define Bn 32
#define Tn 65536
#define TILE 2048
#define NT 32              /* tiles per row in k_seg */
#define ROUNDS 8           /* TILE/256 */
#define SEGCAP (Tn + 2)

#define MBTH 512
#define MWARPS 16
#define CPR 128            /* chunks per row = Tn/MBTH */
#define NBLK (Bn * CPR)    /* 4096 */

// ---------------- scratch (device globals) ----------------
static __device__ unsigned short g_segids[Bn * Tn];   // 4 MB
static __device__ int    g_S[Bn * SEGCAP];            // segment start positions
static __device__ float4 g_Bnd[Bn * SEGCAP];          // excl. param prefix at seg start
static __device__ float  g_xd[Bn * Tn];               // 8 MB  x * distance

static __device__ int    g_tO[Bn * NT];
static __device__ float4 g_tP[Bn * NT];
static __device__ int    g_tflag[Bn * NT];

static __device__ float4 g_aM[NBLK];
static __device__ float2 g_ac[NBLK];
static __device__ int    g_aflag[NBLK];

#define MIN_W_F     0.007853981633974483f
#define LOG2_400_F  8.643856189774724f
#define LOG2_20_F   4.321928094887363f

__device__ __forceinline__ float fast_sigmoid(float v) {
    return __fdividef(1.0f, 1.0f + __expf(-v));
}

// N = L after E  (2x2 affine compose)
#define COMPOSE(E00,E01,E10,E11,Ec1,Ec2, L00,L01,L10,L11,Lc1,Lc2, \
                N00,N01,N10,N11,Nc1,Nc2)                          \
    do {                                                          \
        N00 = fmaf(L00, E00, L01 * E10);                          \
        N01 = fmaf(L00, E01, L01 * E11);                          \
        N10 = fmaf(L10, E00, L11 * E10);                          \
        N11 = fmaf(L10, E01, L11 * E11);                          \
        Nc1 = fmaf(L00, Ec1, fmaf(L01, Ec2, Lc1));                \
        Nc2 = fmaf(L10, Ec1, fmaf(L11, Ec2, Lc2));                \
    } while (0)

// =====================================================================
// K1: single-pass segment scan with aggregate publish + lookback.
// =====================================================================
__global__ void __launch_bounds__(256) k_seg(const int* __restrict__ onsets,
                                             const float4* __restrict__ params) {
    int blk = blockIdx.x, tid = threadIdx.x;
    int row = blk >> 5, tile = blk & (NT - 1);
    long rowbase = (long)row * Tn;
    long base = rowbase + (long)tile * TILE;
    int lane = tid & 31, wid = tid >> 5;
    int rowoff = row * SEGCAP;

    __shared__ int    so[8];
    __shared__ float4 sp[8];
    __shared__ int    s_totO;
    __shared__ float4 s_totP;
    __shared__ int    s_carO;
    __shared__ float4 s_carP;

    // ---- pass A: tile aggregates ----
    int o = 0;
    float4 ps = make_float4(0.f, 0.f, 0.f, 0.f);
#pragma unroll
    for (int r = 0; r < ROUNDS; r++) {
        long idx = base + r * 256 + tid;
        o += onsets[idx];
        float4 p = params[idx];
        ps.x += p.x; ps.y += p.y; ps.z += p.z; ps.w += p.w;
    }
#pragma unroll
    for (int off = 16; off; off >>= 1) {
        o    += __shfl_down_sync(~0u, o, off);
        ps.x += __shfl_down_sync(~0u, ps.x, off);
        ps.y += __shfl_down_sync(~0u, ps.y, off);
        ps.z += __shfl_down_sync(~0u, ps.z, off);
        ps.w += __shfl_down_sync(~0u, ps.w, off);
    }
    if (lane == 0) { so[wid] = o; sp[wid] = ps; }
    __syncthreads();
    if (tid == 0) {
        int ot = 0; float4 pt = make_float4(0.f, 0.f, 0.f, 0.f);
#pragma unroll
        for (int w = 0; w < 8; w++) {
            ot += so[w];
            pt.x += sp[w].x; pt.y += sp[w].y; pt.z += sp[w].z; pt.w += sp[w].w;
        }
        s_totO = ot; s_totP = pt;
        g_tO[blk] = ot; g_tP[blk] = pt;
        __threadfence();
        *(volatile int*)&g_tflag[blk] = 1;
    }
    __syncthreads();

    // ---- lookback: sum predecessor tile aggregates (commutative) ----
    if (wid == 0) {
        int co = 0;
        float4 cp = make_float4(0.f, 0.f, 0.f, 0.f);
        if (lane < tile) {
            int pb = (row << 5) + lane;
            while (*(volatile int*)&g_tflag[pb] == 0) {}
            __threadfence();
            co = g_tO[pb];
            cp = g_tP[pb];
        }
#pragma unroll
        for (int off = 16; off; off >>= 1) {
            co   += __shfl_down_sync(~0u, co, off);
            cp.x += __shfl_down_sync(~0u, cp.x, off);
            cp.y += __shfl_down_sync(~0u, cp.y, off);
            cp.z += __shfl_down_sync(~0u, cp.z, off);
            cp.w += __shfl_down_sync(~0u, cp.w, off);
        }
        if (lane == 0) { s_carO = co; s_carP = cp; }
    }
    __syncthreads();
    int    carO = s_carO;
    float4 carP = s_carP;
    if (tid == 0) {
        if (tile == 0) {
            g_S[rowoff] = 0;
            g_Bnd[rowoff] = make_float4(0.f, 0.f, 0.f, 0.f);
        }
        if (tile == NT - 1) {
            int nOn = carO + s_totO;
            g_S[rowoff + nOn + 1] = Tn;
            g_Bnd[rowoff + nOn + 1] = make_float4(carP.x + s_totP.x, carP.y + s_totP.y,
                                                  carP.z + s_totP.z, carP.w + s_totP.w);
        }
    }
    __syncthreads();

    // ---- pass B: in-tile scan (re-read, L2-resident) ----
#pragma unroll
    for (int r = 0; r < ROUNDS; r++) {
        long idx = base + r * 256 + tid;
        int oo = onsets[idx];
        float4 p = params[idx];
        int oi = oo;
        float4 pi = p;
#pragma unroll
        for (int off = 1; off < 32; off <<= 1) {
            int   to = __shfl_up_sync(~0u, oi, off);
            float a  = __shfl_up_sync(~0u, pi.x, off);
            float b  = __shfl_up_sync(~0u, pi.y, off);
            float c  = __shfl_up_sync(~0u, pi.z, off);
            float d  = __shfl_up_sync(~0u, pi.w, off);
            if (lane >= off) { oi += to; pi.x += a; pi.y += b; pi.z += c; pi.w += d; }
        }
        if (lane == 31) { so[wid] = oi; sp[wid] = pi; }
        __syncthreads();
        int wpo = 0, bto = 0;
        float4 wpp = make_float4(0.f, 0.f, 0.f, 0.f);
        float4 btp = make_float4(0.f, 0.f, 0.f, 0.f);
#pragma unroll
        for (int w = 0; w < 8; w++) {
            if (w == wid) { wpo = bto; wpp = btp; }
            bto += so[w];
            btp.x += sp[w].x; btp.y += sp[w].y; btp.z += sp[w].z; btp.w += sp[w].w;
        }
        int id = carO + wpo + oi;
        g_segids[idx] = (unsigned short)id;
        if (oo) {
            g_S[rowoff + id] = (int)(idx - rowbase);
            g_Bnd[rowoff + id] = make_float4(carP.x + wpp.x + pi.x - p.x,
                                             carP.y + wpp.y + pi.y - p.y,
                                             carP.z + wpp.z + pi.z - p.z,
                                             carP.w + wpp.w + pi.w - p.w);
        }
        carO += bto;
        carP.x += btp.x; carP.y += btp.y; carP.z += btp.z; carP.w += btp.w;
        __syncthreads();
    }
}

// =====================================================================
// K2: xd = x * distance(segment-avg param0)
// =====================================================================
__global__ void __launch_bounds__(256) k_xd(const float* __restrict__ x) {
    int idx = blockIdx.x * 256 + threadIdx.x;
    int row = idx >> 16;
    int ro = row * SEGCAP + (int)g_segids[idx];
    float num = g_Bnd[ro + 1].x - g_Bnd[ro].x;
    float den = (float)(g_S[ro + 1] - g_S[ro]);
    float a = num * __fdividef(1.f, fmaxf(den, 1.f));
    float dist = 0.1f * exp2f(fast_sigmoid(a) * LOG2_20_F);
    g_xd[idx] = x[idx] * dist;
}

// =====================================================================
// K3: mega-kernel — coef + block scan + deterministic lookback + output
// =====================================================================
__global__ void __launch_bounds__(MBTH) k_main(const float* __restrict__ f0,
                                               float* __restrict__ out) {
    int blk = blockIdx.x, tid = threadIdx.x;
    int idx = blk * MBTH + tid;
    int row = idx >> 16, t = idx & (Tn - 1);
    int lane = tid & 31, wid = tid >> 5;
    int chunk = blk & (CPR - 1);
    int rowBlk = blk - chunk;

    // ---- coefficients ----
    int ro = row * SEGCAP + (int)g_segids[idx];
    float4 B0 = g_Bnd[ro], B1 = g_Bnd[ro + 1];
    float invc = __fdividef(1.f, fmaxf((float)(g_S[ro + 1] - g_S[ro]), 1.f));
    float wmod = fast_sigmoid((B1.y - B0.y) * invc);
    float qmod = fast_sigmoid((B1.z - B0.z) * invc);
    float mu   = fast_sigmoid((B1.w - B0.w) * invc);

    float p = f0[idx] * mu;
    float z = floorf(p);
    float alfa = p - z;
    int zi = (int)z;
    int j1 = t - zi - 1, j2 = t - zi - 2;
    int rb = row << 16;
    float xd0 = g_xd[idx];
    float x1 = (j1 >= 0) ? g_xd[rb + j1] : 0.f;
    float x2 = (j2 >= 0) ? g_xd[rb + j2] : 0.f;
    float xc = xd0 - (1.f - alfa) * x1 - alfa * x2;

    float w = MIN_W_F * exp2f(wmod * LOG2_400_F);
    float q = 0.1f * exp2f(qmod * LOG2_20_F);
    float sh, ch;
    __sincosf(0.5f * w, &sh, &ch);
    float omc = 2.f * sh * sh;          // 1 - cos(w)
    float cw = 1.f - omc;
    float sw = 2.f * sh * ch;
    float alpha = __fdividef(sw, 2.f * q);
    float inva0 = __fdividef(1.f, 1.f + alpha);
    float b0 = 0.5f * omc * inva0;
    float b1c = omc * inva0;
    float a1 = -2.f * cw * inva0;
    float a2 = (1.f - alpha) * inva0;
    float m00 = -a1, m10 = -a2;
    float bx = b0 * xc;
    float Cc1 = (b1c - a1 * b0) * xc;
    float Cc2 = (b0 - a2 * b0) * xc;    // b2 == b0

    // ---- warp inclusive scan of affine steps ----
    float A00 = m00, A01 = 1.f, A10 = m10, A11 = 0.f, Ac1 = Cc1, Ac2 = Cc2;
#pragma unroll
    for (int off = 1; off < 32; off <<= 1) {
        float E00 = __shfl_up_sync(~0u, A00, off);
        float E01 = __shfl_up_sync(~0u, A01, off);
        float E10 = __shfl_up_sync(~0u, A10, off);
        float E11 = __shfl_up_sync(~0u, A11, off);
        float Ec1 = __shfl_up_sync(~0u, Ac1, off);
        float Ec2 = __shfl_up_sync(~0u, Ac2, off);
        if (lane >= off) {
            float N00, N01, N10, N11, Nc1, Nc2;
            COMPOSE(E00,E01,E10,E11,Ec1,Ec2, A00,A01,A10,A11,Ac1,Ac2,
                    N00,N01,N10,N11,Nc1,Nc2);
            A00 = N00; A01 = N01; A10 = N10; A11 = N11; Ac1 = Nc1; Ac2 = Nc2;
        }
    }

    __shared__ float sw6[MWARPS][6];
    __shared__ float se6[MWARPS][6];
    __shared__ float2 s_sin;
    if (lane == 31) {
        sw6[wid][0] = A00; sw6[wid][1] = A01; sw6[wid][2] = A10;
        sw6[wid][3] = A11; sw6[wid][4] = Ac1; sw6[wid][5] = Ac2;
    }
    __syncthreads();

    if (wid == 0) {
        // block-level scan over MWARPS warp aggregates (lanes 0..15)
        float W00 = 1.f, W01 = 0.f, W10 = 0.f, W11 = 1.f, Wc1 = 0.f, Wc2 = 0.f;
        if (lane < MWARPS) {
            W00 = sw6[lane][0]; W01 = sw6[lane][1]; W10 = sw6[lane][2];
            W11 = sw6[lane][3]; Wc1 = sw6[lane][4]; Wc2 = sw6[lane][5];
        }
#pragma unroll
        for (int off = 1; off < MWARPS; off <<= 1) {
            float E00 = __shfl_up_sync(~0u, W00, off);
            float E01 = __shfl_up_sync(~0u, W01, off);
            float E10 = __shfl_up_sync(~0u, W10, off);
            float E11 = __shfl_up_sync(~0u, W11, off);
            float Ec1 = __shfl_up_sync(~0u, Wc1, off);
            float Ec2 = __shfl_up_sync(~0u, Wc2, off);
            if (lane >= off && lane < MWARPS) {
                float N00, N01, N10, N11, Nc1, Nc2;
                COMPOSE(E00,E01,E10,E11,Ec1,Ec2, W00,W01,W10,W11,Wc1,Wc2,
                        N00,N01,N10,N11,Nc1,Nc2);
                W00 = N00; W01 = N01; W10 = N10; W11 = N11; Wc1 = Nc1; Wc2 = Nc2;
            }
        }
        // exclusive warp prefixes -> se6
        float P00 = __shfl_up_sync(~0u, W00, 1);
        float P01 = __shfl_up_sync(~0u, W01, 1);
        float P10 = __shfl_up_sync(~0u, W10, 1);
        float P11 = __shfl_up_sync(~0u, W11, 1);
        float Pc1 = __shfl_up_sync(~0u, Wc1, 1);
        float Pc2 = __shfl_up_sync(~0u, Wc2, 1);
        if (lane == 0) { P00 = 1.f; P01 = 0.f; P10 = 0.f; P11 = 1.f; Pc1 = 0.f; Pc2 = 0.f; }
        if (lane < MWARPS) {
            se6[lane][0] = P00; se6[lane][1] = P01; se6[lane][2] = P10;
            se6[lane][3] = P11; se6[lane][4] = Pc1; se6[lane][5] = Pc2;
        }
        // publish block aggregate (lane MWARPS-1 holds it)
        if (lane == MWARPS - 1) {
            g_aM[blk] = make_float4(W00, W01, W10, W11);
            g_ac[blk] = make_float2(Wc1, Wc2);
            __threadfence();
            *(volatile int*)&g_aflag[blk] = 1;
        }

        // ---- deterministic forward-window lookback ----
        float s1 = 0.f, s2 = 0.f;
        int nfull = chunk >> 5, rem = chunk & 31;
        for (int win = 0; win <= nfull; win++) {
            int cnt = (win < nfull) ? 32 : rem;
            if (cnt == 0) break;
            float T00 = 1.f, T01 = 0.f, T10 = 0.f, T11 = 1.f, Tc1 = 0.f, Tc2 = 0.f;
            if (lane < cnt) {
                int pb = rowBlk + (win << 5) + lane;
                while (*(volatile int*)&g_aflag[pb] == 0) {}
                __threadfence();
                float4 M = g_aM[pb];
                float2 C = g_ac[pb];
                T00 = M.x; T01 = M.y; T10 = M.z; T11 = M.w; Tc1 = C.x; Tc2 = C.y;
            }
#pragma unroll
            for (int off = 1; off < 32; off <<= 1) {
                float E00 = __shfl_up_sync(~0u, T00, off);
                float E01 = __shfl_up_sync(~0u, T01, off);
                float E10 = __shfl_up_sync(~0u, T10, off);
                float E11 = __shfl_up_sync(~0u, T11, off);
                float Ec1 = __shfl_up_sync(~0u, Tc1, off);
                float Ec2 = __shfl_up_sync(~0u, Tc2, off);
                if (lane >= off) {
                    float N00, N01, N10, N11, Nc1, Nc2;
                    COMPOSE(E00,E01,E10,E11,Ec1,Ec2, T00,T01,T10,T11,Tc1,Tc2,
                            N00,N01,N10,N11,Nc1,Nc2);
                    T00 = N00; T01 = N01; T10 = N10; T11 = N11; Tc1 = Nc1; Tc2 = Nc2;
                }
            }
            float F00 = __shfl_sync(~0u, T00, 31);
            float F01 = __shfl_sync(~0u, T01, 31);
            float F10 = __shfl_sync(~0u, T10, 31);
            float F11 = __shfl_sync(~0u, T11, 31);
            float Fc1 = __shfl_sync(~0u, Tc1, 31);
            float Fc2 = __shfl_sync(~0u, Tc2, 31);
            float n1 = fmaf(F00, s1, fmaf(F01, s2, Fc1));
            float n2 = fmaf(F10, s1, fmaf(F11, s2, Fc2));
            s1 = n1; s2 = n2;
        }
        if (lane == 0) s_sin = make_float2(s1, s2);
    }
    __syncthreads();
    float2 sin0 = s_sin;

    // lane-exclusive (row 0 of transform only): inclusive of lane-1
    float L00 = __shfl_up_sync(~0u, A00, 1);
    float L01 = __shfl_up_sync(~0u, A01, 1);
    float Lc1 = __shfl_up_sync(~0u, Ac1, 1);
    if (lane == 0) { L00 = 1.f; L01 = 0.f; Lc1 = 0.f; }

    // compose with warp-exclusive prefix E (full), keep only row 0
    float E00 = se6[wid][0], E01 = se6[wid][1], E10 = se6[wid][2];
    float E11 = se6[wid][3], Ec1 = se6[wid][4], Ec2 = se6[wid][5];
    float X00 = fmaf(L00, E00, L01 * E10);
    float X01 = fmaf(L00, E01, L01 * E11);
    float Xc1 = fmaf(L00, Ec1, fmaf(L01, Ec2, Lc1));

    float S1 = fmaf(X00, sin0.x, fmaf(X01, sin0.y, Xc1));
    out[idx] = bx + S1;
}

// =====================================================================
extern "C" void kernel_launch(void* const* d_in, const int* in_sizes, int n_in,
                              void* d_out, int out_size) {
    const float* f0     = (const float*)d_in[0];
    const float* x      = (const float*)d_in[1];
    const float* params = (const float*)d_in[2];
    const int*   onsets = (const int*)d_in[3];
    float* out = (float*)d_out;

    void *pT = nullptr, *pA = nullptr;
    cudaGetSymbolAddress(&pT, g_tflag);
    cudaGetSymbolAddress(&pA, g_aflag);
    cudaMemsetAsync(pT, 0, sizeof(int) * Bn * NT);
    cudaMemsetAsync(pA, 0, sizeof(int) * NBLK);

    k_seg<<<Bn * NT, 256>>>(onsets, (const float4*)params);
    k_xd<<<(Bn * Tn) / 256, 256>>>(x);
    k_main<<<NBLK, MBTH>>>(f0, out);
}

// round 4
// speedup vs baseline: 1.6501x; 1.6501x over previous
#include <cuda_runtime.h>

#define Bn 32
#define Tn 65536
#define TILE 2048
#define NT 32              /* tiles per row */
#define ROUNDS 8           /* TILE/256 */
#define SEGCAP (Tn + 2)
#define NCHUNK 32
#define BTH 256
#define SPT 8              /* Tn/(NCHUNK*BTH) */

// ---------------- scratch (device globals) ----------------
static __device__ int    g_tO[Bn * NT];
static __device__ float4 g_tP[Bn * NT];
static __device__ int    g_nOn[Bn];
static __device__ unsigned short g_segids[Bn * Tn];  // 4 MB
static __device__ int    g_S[Bn * SEGCAP];
static __device__ float4 g_Bnd[Bn * SEGCAP];
static __device__ float4 g_segA[Bn * SEGCAP];        // m00, m10, v1, v2
static __device__ float2 g_segB[Bn * SEGCAP];        // b0, mu
static __device__ float  g_segD[Bn * SEGCAP];        // dist
static __device__ float  g_xd[Bn * Tn];              // 8 MB
static __device__ float4 g_chunkM[Bn * NCHUNK];
static __device__ float2 g_chunkC[Bn * NCHUNK];
static __device__ float2 g_chunkIn[Bn * NCHUNK];

#define MIN_W_F     0.007853981633974483f
#define LOG2_400_F  8.643856189774724f
#define LOG2_20_F   4.321928094887363f

__device__ __forceinline__ float fast_sigmoid(float v) {
    return __fdividef(1.0f, 1.0f + __expf(-v));
}

// N = L after E  (2x2 affine compose)
#define COMPOSE(E00,E01,E10,E11,Ec1,Ec2, L00,L01,L10,L11,Lc1,Lc2, \
                N00,N01,N10,N11,Nc1,Nc2)                          \
    do {                                                          \
        N00 = fmaf(L00, E00, L01 * E10);                          \
        N01 = fmaf(L00, E01, L01 * E11);                          \
        N10 = fmaf(L10, E00, L11 * E10);                          \
        N11 = fmaf(L10, E01, L11 * E11);                          \
        Nc1 = fmaf(L00, Ec1, fmaf(L01, Ec2, Lc1));                \
        Nc2 = fmaf(L10, Ec1, fmaf(L11, Ec2, Lc2));                \
    } while (0)

// =====================================================================
// K1a: per-tile totals (coalesced)
// =====================================================================
__global__ void __launch_bounds__(256) k_tile(const int* __restrict__ onsets,
                                              const float4* __restrict__ params) {
    int blk = blockIdx.x;
    int row = blk >> 5, tile = blk & (NT - 1);
    long base = (long)row * Tn + (long)tile * TILE;
    int tid = threadIdx.x;

    int o = 0;
    float4 ps = make_float4(0.f, 0.f, 0.f, 0.f);
#pragma unroll
    for (int r = 0; r < ROUNDS; r++) {
        long idx = base + r * 256 + tid;
        o += onsets[idx];
        float4 p = params[idx];
        ps.x += p.x; ps.y += p.y; ps.z += p.z; ps.w += p.w;
    }
#pragma unroll
    for (int off = 16; off; off >>= 1) {
        o    += __shfl_down_sync(~0u, o, off);
        ps.x += __shfl_down_sync(~0u, ps.x, off);
        ps.y += __shfl_down_sync(~0u, ps.y, off);
        ps.z += __shfl_down_sync(~0u, ps.z, off);
        ps.w += __shfl_down_sync(~0u, ps.w, off);
    }
    __shared__ int    so[8];
    __shared__ float4 sp[8];
    int lane = tid & 31, wid = tid >> 5;
    if (lane == 0) { so[wid] = o; sp[wid] = ps; }
    __syncthreads();
    if (tid == 0) {
        int ot = 0; float4 pt = make_float4(0.f, 0.f, 0.f, 0.f);
#pragma unroll
        for (int w = 0; w < 8; w++) {
            ot += so[w];
            pt.x += sp[w].x; pt.y += sp[w].y; pt.z += sp[w].z; pt.w += sp[w].w;
        }
        g_tO[blk] = ot;
        g_tP[blk] = pt;
    }
}

// =====================================================================
// K1b: warp-per-row scan of tile totals; row sentinels; nOn
// =====================================================================
__global__ void __launch_bounds__(1024) k_tileScan() {
    int row = threadIdx.x >> 5, lane = threadIdx.x & 31;
    int i = row * NT + lane;
    int o = g_tO[i];
    float4 p = g_tP[i];
    int oi = o;
    float4 pi = p;
#pragma unroll
    for (int off = 1; off < 32; off <<= 1) {
        int   to = __shfl_up_sync(~0u, oi, off);
        float a  = __shfl_up_sync(~0u, pi.x, off);
        float b  = __shfl_up_sync(~0u, pi.y, off);
        float c  = __shfl_up_sync(~0u, pi.z, off);
        float d  = __shfl_up_sync(~0u, pi.w, off);
        if (lane >= off) { oi += to; pi.x += a; pi.y += b; pi.z += c; pi.w += d; }
    }
    g_tO[i] = oi - o;   // exclusive
    g_tP[i] = make_float4(pi.x - p.x, pi.y - p.y, pi.z - p.z, pi.w - p.w);
    if (lane == 31) {
        int nOn = oi;
        g_nOn[row] = nOn;
        g_S[row * SEGCAP + nOn + 1]   = Tn;
        g_Bnd[row * SEGCAP + nOn + 1] = pi;
    }
    if (lane == 0) {
        g_S[row * SEGCAP]   = 0;
        g_Bnd[row * SEGCAP] = make_float4(0.f, 0.f, 0.f, 0.f);
    }
}

// =====================================================================
// K1c: in-tile scan -> segids + boundary scatter (re-read from L2)
// =====================================================================
__global__ void __launch_bounds__(256) k_ids(const int* __restrict__ onsets,
                                             const float4* __restrict__ params) {
    int blk = blockIdx.x;
    int row = blk >> 5, tile = blk & (NT - 1);
    long rowbase = (long)row * Tn;
    long base = rowbase + (long)tile * TILE;
    int tid = threadIdx.x, lane = tid & 31, wid = tid >> 5;
    int rowoff = row * SEGCAP;

    __shared__ int    so[8];
    __shared__ float4 sp[8];

    int    carO = g_tO[blk];
    float4 carP = g_tP[blk];

#pragma unroll
    for (int r = 0; r < ROUNDS; r++) {
        long idx = base + r * 256 + tid;
        int oo = onsets[idx];
        float4 p = params[idx];
        int oi = oo;
        float4 pi = p;
#pragma unroll
        for (int off = 1; off < 32; off <<= 1) {
            int   to = __shfl_up_sync(~0u, oi, off);
            float a  = __shfl_up_sync(~0u, pi.x, off);
            float b  = __shfl_up_sync(~0u, pi.y, off);
            float c  = __shfl_up_sync(~0u, pi.z, off);
            float d  = __shfl_up_sync(~0u, pi.w, off);
            if (lane >= off) { oi += to; pi.x += a; pi.y += b; pi.z += c; pi.w += d; }
        }
        if (lane == 31) { so[wid] = oi; sp[wid] = pi; }
        __syncthreads();
        int wpo = 0, bto = 0;
        float4 wpp = make_float4(0.f, 0.f, 0.f, 0.f);
        float4 btp = make_float4(0.f, 0.f, 0.f, 0.f);
#pragma unroll
        for (int w = 0; w < 8; w++) {
            if (w == wid) { wpo = bto; wpp = btp; }
            bto += so[w];
            btp.x += sp[w].x; btp.y += sp[w].y; btp.z += sp[w].z; btp.w += sp[w].w;
        }
        int id = carO + wpo + oi;
        g_segids[idx] = (unsigned short)id;
        if (oo) {
            g_S[rowoff + id] = (int)(idx - rowbase);
            g_Bnd[rowoff + id] = make_float4(carP.x + wpp.x + pi.x - p.x,
                                             carP.y + wpp.y + pi.y - p.y,
                                             carP.z + wpp.z + pi.z - p.z,
                                             carP.w + wpp.w + pi.w - p.w);
        }
        carO += bto;
        carP.x += btp.x; carP.y += btp.y; carP.z += btp.z; carP.w += btp.w;
        __syncthreads();
    }
}

// =====================================================================
// K2: per-SEGMENT coefficients (all MUFU here; ~2K segments total)
// =====================================================================
__global__ void __launch_bounds__(256) k_segc() {
    int row = blockIdx.x;
    int rowoff = row * SEGCAP;
    int nOn = g_nOn[row];
    for (int s = threadIdx.x; s <= nOn; s += 256) {
        int ro = rowoff + s;
        float4 B0 = g_Bnd[ro], B1 = g_Bnd[ro + 1];
        float den = (float)(g_S[ro + 1] - g_S[ro]);
        float invc = __fdividef(1.f, fmaxf(den, 1.f));
        float dist = 0.1f * exp2f(fast_sigmoid((B1.x - B0.x) * invc) * LOG2_20_F);
        float wmod = fast_sigmoid((B1.y - B0.y) * invc);
        float qmod = fast_sigmoid((B1.z - B0.z) * invc);
        float mu   = fast_sigmoid((B1.w - B0.w) * invc);

        float w = MIN_W_F * exp2f(wmod * LOG2_400_F);
        float q = 0.1f * exp2f(qmod * LOG2_20_F);
        float sh, ch;
        __sincosf(0.5f * w, &sh, &ch);
        float omc = 2.f * sh * sh;      // 1 - cos(w)
        float cw = 1.f - omc;
        float sw = 2.f * sh * ch;
        float alpha = __fdividef(sw, 2.f * q);
        float inva0 = __fdividef(1.f, 1.f + alpha);
        float b0 = 0.5f * omc * inva0;
        float b1c = omc * inva0;
        float a1 = -2.f * cw * inva0;
        float a2 = (1.f - alpha) * inva0;

        g_segA[ro] = make_float4(-a1, -a2, b1c - a1 * b0, b0 - a2 * b0);
        g_segB[ro] = make_float2(b0, mu);
        g_segD[ro] = dist;
    }
}

// =====================================================================
// K3: xd = x * dist[segid]
// =====================================================================
__global__ void __launch_bounds__(256) k_xd(const float* __restrict__ x) {
    int idx = blockIdx.x * 256 + threadIdx.x;
    int row = idx >> 16;
    int ro = row * SEGCAP + (int)g_segids[idx];
    g_xd[idx] = x[idx] * g_segD[ro];
}

// =====================================================================
// per-sample affine step from segment table + comb
// =====================================================================
__device__ __forceinline__ void make_step(int idx, const float* __restrict__ f0,
                                          float4& M, float& xc_out) {
    int row = idx >> 16;
    int t = idx & (Tn - 1);
    int ro = row * SEGCAP + (int)g_segids[idx];
    float4 A = g_segA[ro];
    float2 Bc = g_segB[ro];
    float p = f0[idx] * Bc.y;
    float z = floorf(p);
    float alfa = p - z;
    int zi = (int)z;
    int j1 = t - zi - 1, j2 = t - zi - 2;
    int rb = row << 16;
    float xd0 = g_xd[idx];
    float x1 = (j1 >= 0) ? g_xd[rb + j1] : 0.f;
    float x2 = (j2 >= 0) ? g_xd[rb + j2] : 0.f;
    float xc = xd0 - (1.f - alfa) * x1 - alfa * x2;
    M = make_float4(A.x, A.y, A.z * xc, A.w * xc);
    xc_out = xc;
}

__device__ __forceinline__ void compose_regs(const float4 m[SPT],
        float& A00, float& A01, float& A10, float& A11, float& c1, float& c2) {
    A00 = 1.f; A01 = 0.f; A10 = 0.f; A11 = 1.f; c1 = 0.f; c2 = 0.f;
#pragma unroll
    for (int i = 0; i < SPT; i++) {
        float n00 = fmaf(m[i].x, A00, A10);
        float n01 = fmaf(m[i].x, A01, A11);
        float n10 = m[i].y * A00;
        float n11 = m[i].y * A01;
        float t1  = fmaf(m[i].x, c1, c2) + m[i].z;
        float t2  = fmaf(m[i].y, c1, m[i].w);
        A00 = n00; A01 = n01; A10 = n10; A11 = n11; c1 = t1; c2 = t2;
    }
}

// =====================================================================
// K4: per-chunk total transform (ordered tree reduce)
// =====================================================================
__global__ void __launch_bounds__(BTH) k_scanA(const float* __restrict__ f0) {
    int tid = threadIdx.x;
    int base = blockIdx.x * (BTH * SPT) + tid * SPT;
    float4 m[SPT];
    float xcv;
#pragma unroll
    for (int i = 0; i < SPT; i++) make_step(base + i, f0, m[i], xcv);
    float A00, A01, A10, A11, c1, c2;
    compose_regs(m, A00, A01, A10, A11, c1, c2);

    __shared__ float s00[BTH], s01[BTH], s10[BTH], s11[BTH], sc1[BTH], sc2[BTH];
    s00[tid] = A00; s01[tid] = A01; s10[tid] = A10; s11[tid] = A11;
    sc1[tid] = c1;  sc2[tid] = c2;
    for (int st = 1; st < BTH; st <<= 1) {
        __syncthreads();
        if ((tid & (2 * st - 1)) == 0) {
            int j = tid + st;
            float N00, N01, N10, N11, Nc1, Nc2;
            COMPOSE(s00[tid],s01[tid],s10[tid],s11[tid],sc1[tid],sc2[tid],
                    s00[j],  s01[j],  s10[j],  s11[j],  sc1[j],  sc2[j],
                    N00,N01,N10,N11,Nc1,Nc2);
            s00[tid] = N00; s01[tid] = N01; s10[tid] = N10; s11[tid] = N11;
            sc1[tid] = Nc1; sc2[tid] = Nc2;
        }
    }
    __syncthreads();
    if (tid == 0) {
        g_chunkM[blockIdx.x] = make_float4(s00[0], s01[0], s10[0], s11[0]);
        g_chunkC[blockIdx.x] = make_float2(sc1[0], sc2[0]);
    }
}

// =====================================================================
// K5: warp-per-row Kogge-Stone over chunk transforms
// =====================================================================
__global__ void __launch_bounds__(1024) k_scanB() {
    int l = threadIdx.x & 31;
    int i = threadIdx.x;   // row = tid>>5, chunk = lane; NCHUNK==32
    float4 M = g_chunkM[i];
    float2 c = g_chunkC[i];
    float A00 = M.x, A01 = M.y, A10 = M.z, A11 = M.w, c1 = c.x, c2 = c.y;
#pragma unroll
    for (int off = 1; off < 32; off <<= 1) {
        float E00 = __shfl_up_sync(~0u, A00, off);
        float E01 = __shfl_up_sync(~0u, A01, off);
        float E10 = __shfl_up_sync(~0u, A10, off);
        float E11 = __shfl_up_sync(~0u, A11, off);
        float Ec1 = __shfl_up_sync(~0u, c1, off);
        float Ec2 = __shfl_up_sync(~0u, c2, off);
        if (l >= off) {
            float N00, N01, N10, N11, Nc1, Nc2;
            COMPOSE(E00,E01,E10,E11,Ec1,Ec2, A00,A01,A10,A11,c1,c2,
                    N00,N01,N10,N11,Nc1,Nc2);
            A00 = N00; A01 = N01; A10 = N10; A11 = N11; c1 = Nc1; c2 = Nc2;
        }
    }
    float p1 = __shfl_up_sync(~0u, c1, 1);
    float p2 = __shfl_up_sync(~0u, c2, 1);
    if (l == 0) { p1 = 0.f; p2 = 0.f; }
    g_chunkIn[i] = make_float2(p1, p2);
}

// =====================================================================
// K6: block KS scan -> per-thread incoming state -> replay + output
// =====================================================================
__global__ void __launch_bounds__(BTH) k_replay(const float* __restrict__ f0,
                                                float* __restrict__ out) {
    int tid = threadIdx.x;
    int base = blockIdx.x * (BTH * SPT) + tid * SPT;
    float4 m[SPT];
    float xc[SPT];
#pragma unroll
    for (int i = 0; i < SPT; i++) make_step(base + i, f0, m[i], xc[i]);
    float r00, r01, r10, r11, rc1, rc2;
    compose_regs(m, r00, r01, r10, r11, rc1, rc2);

    __shared__ float s00[BTH], s01[BTH], s10[BTH], s11[BTH], sc1[BTH], sc2[BTH];
    s00[tid] = r00; s01[tid] = r01; s10[tid] = r10; s11[tid] = r11;
    sc1[tid] = rc1; sc2[tid] = rc2;
    __syncthreads();
    for (int st = 1; st < BTH; st <<= 1) {
        float E00 = 0.f, E01 = 0.f, E10 = 0.f, E11 = 0.f, Ec1 = 0.f, Ec2 = 0.f;
        bool has = (tid >= st);
        if (has) {
            E00 = s00[tid - st]; E01 = s01[tid - st];
            E10 = s10[tid - st]; E11 = s11[tid - st];
            Ec1 = sc1[tid - st]; Ec2 = sc2[tid - st];
        }
        __syncthreads();
        if (has) {
            float N00, N01, N10, N11, Nc1, Nc2;
            COMPOSE(E00,E01,E10,E11,Ec1,Ec2, r00,r01,r10,r11,rc1,rc2,
                    N00,N01,N10,N11,Nc1,Nc2);
            r00 = N00; r01 = N01; r10 = N10; r11 = N11; rc1 = Nc1; rc2 = Nc2;
            s00[tid] = r00; s01[tid] = r01; s10[tid] = r10; s11[tid] = r11;
            sc1[tid] = rc1; sc2[tid] = rc2;
        }
        __syncthreads();
    }
    float P00 = 1.f, P01 = 0.f, P10 = 0.f, P11 = 1.f, pc1 = 0.f, pc2 = 0.f;
    if (tid > 0) {
        P00 = s00[tid - 1]; P01 = s01[tid - 1];
        P10 = s10[tid - 1]; P11 = s11[tid - 1];
        pc1 = sc1[tid - 1]; pc2 = sc2[tid - 1];
    }
    float2 cin = g_chunkIn[blockIdx.x];
    float st1 = fmaf(P00, cin.x, fmaf(P01, cin.y, pc1));
    float st2 = fmaf(P10, cin.x, fmaf(P11, cin.y, pc2));

    // per-sample b0 is segment-constant: reload (L1-hot) to form bx = b0*xc
    int row = base >> 16;
    int rowoff = row * SEGCAP;
#pragma unroll
    for (int i = 0; i < SPT; i++) {
        int ro = rowoff + (int)g_segids[base + i];
        float b0 = g_segB[ro].x;
        out[base + i] = fmaf(b0, xc[i], st1);
        float n1 = fmaf(m[i].x, st1, st2) + m[i].z;
        float n2 = fmaf(m[i].y, st1, m[i].w);
        st1 = n1; st2 = n2;
    }
}

// =====================================================================
extern "C" void kernel_launch(void* const* d_in, const int* in_sizes, int n_in,
                              void* d_out, int out_size) {
    const float* f0     = (const float*)d_in[0];
    const float* x      = (const float*)d_in[1];
    const float* params = (const float*)d_in[2];
    const int*   onsets = (const int*)d_in[3];
    float* out = (float*)d_out;

    k_tile<<<Bn * NT, 256>>>(onsets, (const float4*)params);
    k_tileScan<<<1, 1024>>>();
    k_ids<<<Bn * NT, 256>>>(onsets, (const float4*)params);
    k_segc<<<Bn, 256>>>();
    k_xd<<<(Bn * Tn) / 256, 256>>>(x);
    k_scanA<<<Bn * NCHUNK, BTH>>>(f0);
    k_scanB<<<1, 1024>>>();
    k_replay<<<Bn * NCHUNK, BTH>>>(f0, out);
}

// round 5
// speedup vs baseline: 1.7069x; 1.0344x over previous
#include <cuda_runtime.h>

#define Bn 32
#define Tn 65536
#define TILE 2048
#define NT 32              /* tiles per row */
#define ROUNDS 8           /* TILE/256 */
#define SEGCAP (Tn + 2)
#define NCHUNK 32
#define BTH 256
#define SPT 8              /* Tn/(NCHUNK*BTH) */

// ---------------- scratch (device globals) ----------------
static __device__ int    g_tO[Bn * NT];
static __device__ float4 g_tP[Bn * NT];
static __device__ int    g_nOn[Bn];
static __device__ unsigned short g_segids[Bn * Tn];  // 4 MB
static __device__ int    g_S[Bn * SEGCAP];
static __device__ float4 g_Bnd[Bn * SEGCAP];
static __device__ float4 g_segA[Bn * SEGCAP];        // m00, m10, v1, v2
static __device__ float2 g_segB[Bn * SEGCAP];        // b0, mu
static __device__ float  g_xd[Bn * Tn];              // 8 MB
static __device__ float4 g_chunkM[Bn * NCHUNK];
static __device__ float2 g_chunkC[Bn * NCHUNK];

#define MIN_W_F     0.007853981633974483f
#define LOG2_400_F  8.643856189774724f
#define LOG2_20_F   4.321928094887363f

__device__ __forceinline__ float fast_sigmoid(float v) {
    return __fdividef(1.0f, 1.0f + __expf(-v));
}

// N = L after E  (2x2 affine compose)
#define COMPOSE(E00,E01,E10,E11,Ec1,Ec2, L00,L01,L10,L11,Lc1,Lc2, \
                N00,N01,N10,N11,Nc1,Nc2)                          \
    do {                                                          \
        N00 = fmaf(L00, E00, L01 * E10);                          \
        N01 = fmaf(L00, E01, L01 * E11);                          \
        N10 = fmaf(L10, E00, L11 * E10);                          \
        N11 = fmaf(L10, E01, L11 * E11);                          \
        Nc1 = fmaf(L00, Ec1, fmaf(L01, Ec2, Lc1));                \
        Nc2 = fmaf(L10, Ec1, fmaf(L11, Ec2, Lc2));                \
    } while (0)

// =====================================================================
// K1: per-tile totals (coalesced)
// =====================================================================
__global__ void __launch_bounds__(256) k_tile(const int* __restrict__ onsets,
                                              const float4* __restrict__ params) {
    int blk = blockIdx.x;
    int row = blk >> 5, tile = blk & (NT - 1);
    long base = (long)row * Tn + (long)tile * TILE;
    int tid = threadIdx.x;

    int o = 0;
    float4 ps = make_float4(0.f, 0.f, 0.f, 0.f);
#pragma unroll
    for (int r = 0; r < ROUNDS; r++) {
        long idx = base + r * 256 + tid;
        o += onsets[idx];
        float4 p = params[idx];
        ps.x += p.x; ps.y += p.y; ps.z += p.z; ps.w += p.w;
    }
#pragma unroll
    for (int off = 16; off; off >>= 1) {
        o    += __shfl_down_sync(~0u, o, off);
        ps.x += __shfl_down_sync(~0u, ps.x, off);
        ps.y += __shfl_down_sync(~0u, ps.y, off);
        ps.z += __shfl_down_sync(~0u, ps.z, off);
        ps.w += __shfl_down_sync(~0u, ps.w, off);
    }
    __shared__ int    so[8];
    __shared__ float4 sp[8];
    int lane = tid & 31, wid = tid >> 5;
    if (lane == 0) { so[wid] = o; sp[wid] = ps; }
    __syncthreads();
    if (tid == 0) {
        int ot = 0; float4 pt = make_float4(0.f, 0.f, 0.f, 0.f);
#pragma unroll
        for (int w = 0; w < 8; w++) {
            ot += so[w];
            pt.x += sp[w].x; pt.y += sp[w].y; pt.z += sp[w].z; pt.w += sp[w].w;
        }
        g_tO[blk] = ot;
        g_tP[blk] = pt;
    }
}

// =====================================================================
// K2: in-tile scan -> segids + boundary scatter.
//     Warp 0 derives the tile-exclusive carry from predecessor tile
//     aggregates (written by K1, kernel-boundary safe).
// =====================================================================
__global__ void __launch_bounds__(256) k_ids(const int* __restrict__ onsets,
                                             const float4* __restrict__ params) {
    int blk = blockIdx.x;
    int row = blk >> 5, tile = blk & (NT - 1);
    long rowbase = (long)row * Tn;
    long base = rowbase + (long)tile * TILE;
    int tid = threadIdx.x, lane = tid & 31, wid = tid >> 5;
    int rowoff = row * SEGCAP;

    __shared__ int    so[8];
    __shared__ float4 sp[8];
    __shared__ int    s_carO;
    __shared__ float4 s_carP;

    // warp 0: carry = sum of predecessor tile aggregates (fixed-tree, deterministic)
    if (wid == 0) {
        int co = 0;
        float4 cp = make_float4(0.f, 0.f, 0.f, 0.f);
        if (lane < tile) {
            int pb = (row << 5) + lane;
            co = g_tO[pb];
            cp = g_tP[pb];
        }
#pragma unroll
        for (int off = 16; off; off >>= 1) {
            co   += __shfl_down_sync(~0u, co, off);
            cp.x += __shfl_down_sync(~0u, cp.x, off);
            cp.y += __shfl_down_sync(~0u, cp.y, off);
            cp.z += __shfl_down_sync(~0u, cp.z, off);
            cp.w += __shfl_down_sync(~0u, cp.w, off);
        }
        if (lane == 0) { s_carO = co; s_carP = cp; }
    }
    __syncthreads();
    int    carO = s_carO;
    float4 carP = s_carP;
    if (tid == 0 && tile == 0) {
        g_S[rowoff] = 0;
        g_Bnd[rowoff] = make_float4(0.f, 0.f, 0.f, 0.f);
    }

#pragma unroll
    for (int r = 0; r < ROUNDS; r++) {
        long idx = base + r * 256 + tid;
        int oo = onsets[idx];
        float4 p = params[idx];
        int oi = oo;
        float4 pi = p;
#pragma unroll
        for (int off = 1; off < 32; off <<= 1) {
            int   to = __shfl_up_sync(~0u, oi, off);
            float a  = __shfl_up_sync(~0u, pi.x, off);
            float b  = __shfl_up_sync(~0u, pi.y, off);
            float c  = __shfl_up_sync(~0u, pi.z, off);
            float d  = __shfl_up_sync(~0u, pi.w, off);
            if (lane >= off) { oi += to; pi.x += a; pi.y += b; pi.z += c; pi.w += d; }
        }
        if (lane == 31) { so[wid] = oi; sp[wid] = pi; }
        __syncthreads();
        int wpo = 0, bto = 0;
        float4 wpp = make_float4(0.f, 0.f, 0.f, 0.f);
        float4 btp = make_float4(0.f, 0.f, 0.f, 0.f);
#pragma unroll
        for (int w = 0; w < 8; w++) {
            if (w == wid) { wpo = bto; wpp = btp; }
            bto += so[w];
            btp.x += sp[w].x; btp.y += sp[w].y; btp.z += sp[w].z; btp.w += sp[w].w;
        }
        int id = carO + wpo + oi;
        g_segids[idx] = (unsigned short)id;
        if (oo) {
            g_S[rowoff + id] = (int)(idx - rowbase);
            g_Bnd[rowoff + id] = make_float4(carP.x + wpp.x + pi.x - p.x,
                                             carP.y + wpp.y + pi.y - p.y,
                                             carP.z + wpp.z + pi.z - p.z,
                                             carP.w + wpp.w + pi.w - p.w);
        }
        carO += bto;
        carP.x += btp.x; carP.y += btp.y; carP.z += btp.z; carP.w += btp.w;
        __syncthreads();
    }

    // tile 31 writes row sentinels (carO/carP now hold row totals)
    if (tid == 0 && tile == NT - 1) {
        g_nOn[row] = carO;
        g_S[rowoff + carO + 1]   = Tn;
        g_Bnd[rowoff + carO + 1] = carP;
    }
}

// =====================================================================
// K3: xd = x * dist (inline); blocks 0..Bn-1 also build per-segment
//     coefficient tables (all MUFU-heavy math once per segment).
// =====================================================================
__global__ void __launch_bounds__(256) k_xd(const float* __restrict__ x) {
    int idx = blockIdx.x * 256 + threadIdx.x;
    int row = idx >> 16;
    int ro = row * SEGCAP + (int)g_segids[idx];
    float num = g_Bnd[ro + 1].x - g_Bnd[ro].x;
    float den = (float)(g_S[ro + 1] - g_S[ro]);
    float a = num * __fdividef(1.f, fmaxf(den, 1.f));
    float dist = 0.1f * exp2f(fast_sigmoid(a) * LOG2_20_F);
    g_xd[idx] = x[idx] * dist;

    // fused per-segment coefficient table (blocks 0..31, one row each)
    if (blockIdx.x < Bn) {
        int srow = blockIdx.x;
        int rowoff = srow * SEGCAP;
        int nOn = g_nOn[srow];
        for (int s = threadIdx.x; s <= nOn; s += 256) {
            int r2 = rowoff + s;
            float4 B0 = g_Bnd[r2], B1 = g_Bnd[r2 + 1];
            float d2 = (float)(g_S[r2 + 1] - g_S[r2]);
            float invc = __fdividef(1.f, fmaxf(d2, 1.f));
            float wmod = fast_sigmoid((B1.y - B0.y) * invc);
            float qmod = fast_sigmoid((B1.z - B0.z) * invc);
            float mu   = fast_sigmoid((B1.w - B0.w) * invc);

            float w = MIN_W_F * exp2f(wmod * LOG2_400_F);
            float q = 0.1f * exp2f(qmod * LOG2_20_F);
            float sh, ch;
            __sincosf(0.5f * w, &sh, &ch);
            float omc = 2.f * sh * sh;      // 1 - cos(w)
            float cw = 1.f - omc;
            float sw = 2.f * sh * ch;
            float alpha = __fdividef(sw, 2.f * q);
            float inva0 = __fdividef(1.f, 1.f + alpha);
            float b0 = 0.5f * omc * inva0;
            float b1c = omc * inva0;
            float a1 = -2.f * cw * inva0;
            float a2 = (1.f - alpha) * inva0;

            g_segA[r2] = make_float4(-a1, -a2, b1c - a1 * b0, b0 - a2 * b0);
            g_segB[r2] = make_float2(b0, mu);
        }
    }
}

// =====================================================================
// per-sample affine step from segment table + comb
// =====================================================================
__device__ __forceinline__ void make_step(int idx, const float* __restrict__ f0,
                                          float4& M, float& xc_out) {
    int row = idx >> 16;
    int t = idx & (Tn - 1);
    int ro = row * SEGCAP + (int)g_segids[idx];
    float4 A = g_segA[ro];
    float2 Bc = g_segB[ro];
    float p = f0[idx] * Bc.y;
    float z = floorf(p);
    float alfa = p - z;
    int zi = (int)z;
    int j1 = t - zi - 1, j2 = t - zi - 2;
    int rb = row << 16;
    float xd0 = g_xd[idx];
    float x1 = (j1 >= 0) ? g_xd[rb + j1] : 0.f;
    float x2 = (j2 >= 0) ? g_xd[rb + j2] : 0.f;
    float xc = xd0 - (1.f - alfa) * x1 - alfa * x2;
    M = make_float4(A.x, A.y, A.z * xc, A.w * xc);
    xc_out = xc;
}

__device__ __forceinline__ void compose_regs(const float4 m[SPT],
        float& A00, float& A01, float& A10, float& A11, float& c1, float& c2) {
    A00 = 1.f; A01 = 0.f; A10 = 0.f; A11 = 1.f; c1 = 0.f; c2 = 0.f;
#pragma unroll
    for (int i = 0; i < SPT; i++) {
        float n00 = fmaf(m[i].x, A00, A10);
        float n01 = fmaf(m[i].x, A01, A11);
        float n10 = m[i].y * A00;
        float n11 = m[i].y * A01;
        float t1  = fmaf(m[i].x, c1, c2) + m[i].z;
        float t2  = fmaf(m[i].y, c1, m[i].w);
        A00 = n00; A01 = n01; A10 = n10; A11 = n11; c1 = t1; c2 = t2;
    }
}

// =====================================================================
// K4: per-chunk total transform (ordered tree reduce)
// =====================================================================
__global__ void __launch_bounds__(BTH) k_scanA(const float* __restrict__ f0) {
    int tid = threadIdx.x;
    int base = blockIdx.x * (BTH * SPT) + tid * SPT;
    float4 m[SPT];
    float xcv;
#pragma unroll
    for (int i = 0; i < SPT; i++) make_step(base + i, f0, m[i], xcv);
    float A00, A01, A10, A11, c1, c2;
    compose_regs(m, A00, A01, A10, A11, c1, c2);

    __shared__ float s00[BTH], s01[BTH], s10[BTH], s11[BTH], sc1[BTH], sc2[BTH];
    s00[tid] = A00; s01[tid] = A01; s10[tid] = A10; s11[tid] = A11;
    sc1[tid] = c1;  sc2[tid] = c2;
    for (int st = 1; st < BTH; st <<= 1) {
        __syncthreads();
        if ((tid & (2 * st - 1)) == 0) {
            int j = tid + st;
            float N00, N01, N10, N11, Nc1, Nc2;
            COMPOSE(s00[tid],s01[tid],s10[tid],s11[tid],sc1[tid],sc2[tid],
                    s00[j],  s01[j],  s10[j],  s11[j],  sc1[j],  sc2[j],
                    N00,N01,N10,N11,Nc1,Nc2);
            s00[tid] = N00; s01[tid] = N01; s10[tid] = N10; s11[tid] = N11;
            sc1[tid] = Nc1; sc2[tid] = Nc2;
        }
    }
    __syncthreads();
    if (tid == 0) {
        g_chunkM[blockIdx.x] = make_float4(s00[0], s01[0], s10[0], s11[0]);
        g_chunkC[blockIdx.x] = make_float2(sc1[0], sc2[0]);
    }
}

// =====================================================================
// K5: block scan + incoming state (warp-0 KS over predecessor chunk
//     aggregates, written by K4) + replay + output
// =====================================================================
__global__ void __launch_bounds__(BTH) k_replay(const float* __restrict__ f0,
                                                float* __restrict__ out) {
    int tid = threadIdx.x, lane = tid & 31, wid = tid >> 5;
    int blk = blockIdx.x;
    int base = blk * (BTH * SPT) + tid * SPT;
    float4 m[SPT];
    float xc[SPT];
#pragma unroll
    for (int i = 0; i < SPT; i++) make_step(base + i, f0, m[i], xc[i]);
    float r00, r01, r10, r11, rc1, rc2;
    compose_regs(m, r00, r01, r10, r11, rc1, rc2);

    __shared__ float s00[BTH], s01[BTH], s10[BTH], s11[BTH], sc1[BTH], sc2[BTH];
    __shared__ float2 s_cin;

    // warp 0: incoming state from predecessor chunk aggregates (same row)
    if (wid == 0) {
        int chunk = blk & (NCHUNK - 1);
        int rowBlk = blk - chunk;
        float T00 = 1.f, T01 = 0.f, T10 = 0.f, T11 = 1.f, Tc1 = 0.f, Tc2 = 0.f;
        if (lane < chunk) {
            float4 M = g_chunkM[rowBlk + lane];
            float2 C = g_chunkC[rowBlk + lane];
            T00 = M.x; T01 = M.y; T10 = M.z; T11 = M.w; Tc1 = C.x; Tc2 = C.y;
        }
#pragma unroll
        for (int off = 1; off < 32; off <<= 1) {
            float E00 = __shfl_up_sync(~0u, T00, off);
            float E01 = __shfl_up_sync(~0u, T01, off);
            float E10 = __shfl_up_sync(~0u, T10, off);
            float E11 = __shfl_up_sync(~0u, T11, off);
            float Ec1 = __shfl_up_sync(~0u, Tc1, off);
            float Ec2 = __shfl_up_sync(~0u, Tc2, off);
            if (lane >= off) {
                float N00, N01, N10, N11, Nc1, Nc2;
                COMPOSE(E00,E01,E10,E11,Ec1,Ec2, T00,T01,T10,T11,Tc1,Tc2,
                        N00,N01,N10,N11,Nc1,Nc2);
                T00 = N00; T01 = N01; T10 = N10; T11 = N11; Tc1 = Nc1; Tc2 = Nc2;
            }
        }
        // initial state is 0 -> incoming = c-part of product over chunks [0, chunk)
        float i1 = 0.f, i2 = 0.f;
        if (chunk > 0) {
            i1 = __shfl_sync(~0u, Tc1, chunk - 1);
            i2 = __shfl_sync(~0u, Tc2, chunk - 1);
        }
        if (lane == 0) s_cin = make_float2(i1, i2);
    }

    s00[tid] = r00; s01[tid] = r01; s10[tid] = r10; s11[tid] = r11;
    sc1[tid] = rc1; sc2[tid] = rc2;
    __syncthreads();
    for (int st = 1; st < BTH; st <<= 1) {
        float E00 = 0.f, E01 = 0.f, E10 = 0.f, E11 = 0.f, Ec1 = 0.f, Ec2 = 0.f;
        bool has = (tid >= st);
        if (has) {
            E00 = s00[tid - st]; E01 = s01[tid - st];
            E10 = s10[tid - st]; E11 = s11[tid - st];
            Ec1 = sc1[tid - st]; Ec2 = sc2[tid - st];
        }
        __syncthreads();
        if (has) {
            float N00, N01, N10, N11, Nc1, Nc2;
            COMPOSE(E00,E01,E10,E11,Ec1,Ec2, r00,r01,r10,r11,rc1,rc2,
                    N00,N01,N10,N11,Nc1,Nc2);
            r00 = N00; r01 = N01; r10 = N10; r11 = N11; rc1 = Nc1; rc2 = Nc2;
            s00[tid] = r00; s01[tid] = r01; s10[tid] = r10; s11[tid] = r11;
            sc1[tid] = rc1; sc2[tid] = rc2;
        }
        __syncthreads();
    }
    float P00 = 1.f, P01 = 0.f, P10 = 0.f, P11 = 1.f, pc1 = 0.f, pc2 = 0.f;
    if (tid > 0) {
        P00 = s00[tid - 1]; P01 = s01[tid - 1];
        P10 = s10[tid - 1]; P11 = s11[tid - 1];
        pc1 = sc1[tid - 1]; pc2 = sc2[tid - 1];
    }
    float2 cin = s_cin;
    float st1 = fmaf(P00, cin.x, fmaf(P01, cin.y, pc1));
    float st2 = fmaf(P10, cin.x, fmaf(P11, cin.y, pc2));

    // replay (b0 per segment, L1-hot)
    int row = base >> 16;
    int rowoff = row * SEGCAP;
#pragma unroll
    for (int i = 0; i < SPT; i++) {
        int ro = rowoff + (int)g_segids[base + i];
        float b0 = g_segB[ro].x;
        out[base + i] = fmaf(b0, xc[i], st1);
        float n1 = fmaf(m[i].x, st1, st2) + m[i].z;
        float n2 = fmaf(m[i].y, st1, m[i].w);
        st1 = n1; st2 = n2;
    }
}

// =====================================================================
extern "C" void kernel_launch(void* const* d_in, const int* in_sizes, int n_in,
                              void* d_out, int out_size) {
    const float* f0     = (const float*)d_in[0];
    const float* x      = (const float*)d_in[1];
    const float* params = (const float*)d_in[2];
    const int*   onsets = (const int*)d_in[3];
    float* out = (float*)d_out;

    k_tile<<<Bn * NT, 256>>>(onsets, (const float4*)params);
    k_ids<<<Bn * NT, 256>>>(onsets, (const float4*)params);
    k_xd<<<(Bn * Tn) / 256, 256>>>(x);
    k_scanA<<<Bn * NCHUNK, BTH>>>(f0);
    k_replay<<<Bn * NCHUNK, BTH>>>(f0, out);
}

// round 6
// speedup vs baseline: 2.1801x; 1.2772x over previous
#include <cuda_runtime.h>

#define Bn 32
#define Tn 65536
#define TILE 2048
#define NT 32              /* tiles per row */
#define ROUNDS 8           /* TILE/256 */
#define SEGCAP (Tn + 2)
#define NCHUNK 32
#define BTH 256
#define SPT 8              /* Tn/(NCHUNK*BTH) */
#define LAG 256            /* staged history for comb (max lag 202) */
#define CHUNKN (BTH * SPT) /* 2048 samples per scan block */

// ---------------- scratch (device globals) ----------------
static __device__ int    g_tO[Bn * NT];
static __device__ float4 g_tP[Bn * NT];
static __device__ int    g_nOn[Bn];
static __device__ unsigned short g_segids[Bn * Tn];  // 4 MB
static __device__ int    g_S[Bn * SEGCAP];
static __device__ float4 g_Bnd[Bn * SEGCAP];
static __device__ float4 g_segA[Bn * SEGCAP];        // m00, m10, v1, v2
static __device__ float2 g_segB[Bn * SEGCAP];        // b0, mu
static __device__ float  g_xd[Bn * Tn];              // 8 MB
static __device__ float  g_xc[Bn * Tn];              // 8 MB (comb output)
static __device__ float4 g_chunkM[Bn * NCHUNK];
static __device__ float2 g_chunkC[Bn * NCHUNK];

#define MIN_W_F     0.007853981633974483f
#define LOG2_400_F  8.643856189774724f
#define LOG2_20_F   4.321928094887363f

__device__ __forceinline__ float fast_sigmoid(float v) {
    return __fdividef(1.0f, 1.0f + __expf(-v));
}

// N = L after E  (2x2 affine compose)
#define COMPOSE(E00,E01,E10,E11,Ec1,Ec2, L00,L01,L10,L11,Lc1,Lc2, \
                N00,N01,N10,N11,Nc1,Nc2)                          \
    do {                                                          \
        N00 = fmaf(L00, E00, L01 * E10);                          \
        N01 = fmaf(L00, E01, L01 * E11);                          \
        N10 = fmaf(L10, E00, L11 * E10);                          \
        N11 = fmaf(L10, E01, L11 * E11);                          \
        Nc1 = fmaf(L00, Ec1, fmaf(L01, Ec2, Lc1));                \
        Nc2 = fmaf(L10, Ec1, fmaf(L11, Ec2, Lc2));                \
    } while (0)

// =====================================================================
// K1: per-tile totals (coalesced)
// =====================================================================
__global__ void __launch_bounds__(256) k_tile(const int* __restrict__ onsets,
                                              const float4* __restrict__ params) {
    int blk = blockIdx.x;
    int row = blk >> 5, tile = blk & (NT - 1);
    long base = (long)row * Tn + (long)tile * TILE;
    int tid = threadIdx.x;

    int o = 0;
    float4 ps = make_float4(0.f, 0.f, 0.f, 0.f);
#pragma unroll
    for (int r = 0; r < ROUNDS; r++) {
        long idx = base + r * 256 + tid;
        o += onsets[idx];
        float4 p = params[idx];
        ps.x += p.x; ps.y += p.y; ps.z += p.z; ps.w += p.w;
    }
#pragma unroll
    for (int off = 16; off; off >>= 1) {
        o    += __shfl_down_sync(~0u, o, off);
        ps.x += __shfl_down_sync(~0u, ps.x, off);
        ps.y += __shfl_down_sync(~0u, ps.y, off);
        ps.z += __shfl_down_sync(~0u, ps.z, off);
        ps.w += __shfl_down_sync(~0u, ps.w, off);
    }
    __shared__ int    so[8];
    __shared__ float4 sp[8];
    int lane = tid & 31, wid = tid >> 5;
    if (lane == 0) { so[wid] = o; sp[wid] = ps; }
    __syncthreads();
    if (tid == 0) {
        int ot = 0; float4 pt = make_float4(0.f, 0.f, 0.f, 0.f);
#pragma unroll
        for (int w = 0; w < 8; w++) {
            ot += so[w];
            pt.x += sp[w].x; pt.y += sp[w].y; pt.z += sp[w].z; pt.w += sp[w].w;
        }
        g_tO[blk] = ot;
        g_tP[blk] = pt;
    }
}

// =====================================================================
// K2: in-tile scan -> segids + boundary scatter. Warp 0 derives carry
//     from predecessor tile aggregates (written by K1).
// =====================================================================
__global__ void __launch_bounds__(256) k_ids(const int* __restrict__ onsets,
                                             const float4* __restrict__ params) {
    int blk = blockIdx.x;
    int row = blk >> 5, tile = blk & (NT - 1);
    long rowbase = (long)row * Tn;
    long base = rowbase + (long)tile * TILE;
    int tid = threadIdx.x, lane = tid & 31, wid = tid >> 5;
    int rowoff = row * SEGCAP;

    __shared__ int    so[8];
    __shared__ float4 sp[8];
    __shared__ int    s_carO;
    __shared__ float4 s_carP;

    if (wid == 0) {
        int co = 0;
        float4 cp = make_float4(0.f, 0.f, 0.f, 0.f);
        if (lane < tile) {
            int pb = (row << 5) + lane;
            co = g_tO[pb];
            cp = g_tP[pb];
        }
#pragma unroll
        for (int off = 16; off; off >>= 1) {
            co   += __shfl_down_sync(~0u, co, off);
            cp.x += __shfl_down_sync(~0u, cp.x, off);
            cp.y += __shfl_down_sync(~0u, cp.y, off);
            cp.z += __shfl_down_sync(~0u, cp.z, off);
            cp.w += __shfl_down_sync(~0u, cp.w, off);
        }
        if (lane == 0) { s_carO = co; s_carP = cp; }
    }
    __syncthreads();
    int    carO = s_carO;
    float4 carP = s_carP;
    if (tid == 0 && tile == 0) {
        g_S[rowoff] = 0;
        g_Bnd[rowoff] = make_float4(0.f, 0.f, 0.f, 0.f);
    }

#pragma unroll
    for (int r = 0; r < ROUNDS; r++) {
        long idx = base + r * 256 + tid;
        int oo = onsets[idx];
        float4 p = params[idx];
        int oi = oo;
        float4 pi = p;
#pragma unroll
        for (int off = 1; off < 32; off <<= 1) {
            int   to = __shfl_up_sync(~0u, oi, off);
            float a  = __shfl_up_sync(~0u, pi.x, off);
            float b  = __shfl_up_sync(~0u, pi.y, off);
            float c  = __shfl_up_sync(~0u, pi.z, off);
            float d  = __shfl_up_sync(~0u, pi.w, off);
            if (lane >= off) { oi += to; pi.x += a; pi.y += b; pi.z += c; pi.w += d; }
        }
        if (lane == 31) { so[wid] = oi; sp[wid] = pi; }
        __syncthreads();
        int wpo = 0, bto = 0;
        float4 wpp = make_float4(0.f, 0.f, 0.f, 0.f);
        float4 btp = make_float4(0.f, 0.f, 0.f, 0.f);
#pragma unroll
        for (int w = 0; w < 8; w++) {
            if (w == wid) { wpo = bto; wpp = btp; }
            bto += so[w];
            btp.x += sp[w].x; btp.y += sp[w].y; btp.z += sp[w].z; btp.w += sp[w].w;
        }
        int id = carO + wpo + oi;
        g_segids[idx] = (unsigned short)id;
        if (oo) {
            g_S[rowoff + id] = (int)(idx - rowbase);
            g_Bnd[rowoff + id] = make_float4(carP.x + wpp.x + pi.x - p.x,
                                             carP.y + wpp.y + pi.y - p.y,
                                             carP.z + wpp.z + pi.z - p.z,
                                             carP.w + wpp.w + pi.w - p.w);
        }
        carO += bto;
        carP.x += btp.x; carP.y += btp.y; carP.z += btp.z; carP.w += btp.w;
        __syncthreads();
    }

    if (tid == 0 && tile == NT - 1) {
        g_nOn[row] = carO;
        g_S[rowoff + carO + 1]   = Tn;
        g_Bnd[rowoff + carO + 1] = carP;
    }
}

// =====================================================================
// K3: xd = x * dist, 4 samples/thread vectorized; blocks 0..Bn-1 also
//     build per-segment coefficient tables.
// =====================================================================
__global__ void __launch_bounds__(256) k_xd(const float4* __restrict__ x4) {
    int v = blockIdx.x * 256 + threadIdx.x;      // float4 index
    int idx = v << 2;
    int row = idx >> 16;
    int rowoff = row * SEGCAP;
    uint2 sv = *(const uint2*)&g_segids[idx];
    int id0 = sv.x & 0xffff, id3 = sv.y >> 16;
    float4 xv = x4[v];
    float4 ov;
    if (id0 == id3) {
        int ro = rowoff + id0;
        float num = g_Bnd[ro + 1].x - g_Bnd[ro].x;
        float den = (float)(g_S[ro + 1] - g_S[ro]);
        float a = num * __fdividef(1.f, fmaxf(den, 1.f));
        float dist = 0.1f * exp2f(fast_sigmoid(a) * LOG2_20_F);
        ov = make_float4(xv.x * dist, xv.y * dist, xv.z * dist, xv.w * dist);
    } else {
        int ids[4] = { (int)(sv.x & 0xffff), (int)(sv.x >> 16),
                       (int)(sv.y & 0xffff), (int)(sv.y >> 16) };
        float* o = &ov.x;
        const float* xi = &xv.x;
#pragma unroll
        for (int i = 0; i < 4; i++) {
            int ro = rowoff + ids[i];
            float num = g_Bnd[ro + 1].x - g_Bnd[ro].x;
            float den = (float)(g_S[ro + 1] - g_S[ro]);
            float a = num * __fdividef(1.f, fmaxf(den, 1.f));
            o[i] = xi[i] * (0.1f * exp2f(fast_sigmoid(a) * LOG2_20_F));
        }
    }
    *(float4*)&g_xd[idx] = ov;

    // fused per-segment coefficient table (blocks 0..31, one row each)
    if (blockIdx.x < Bn) {
        int srow = blockIdx.x;
        int ro0 = srow * SEGCAP;
        int nOn = g_nOn[srow];
        for (int s = threadIdx.x; s <= nOn; s += 256) {
            int r2 = ro0 + s;
            float4 B0 = g_Bnd[r2], B1 = g_Bnd[r2 + 1];
            float d2 = (float)(g_S[r2 + 1] - g_S[r2]);
            float invc = __fdividef(1.f, fmaxf(d2, 1.f));
            float wmod = fast_sigmoid((B1.y - B0.y) * invc);
            float qmod = fast_sigmoid((B1.z - B0.z) * invc);
            float mu   = fast_sigmoid((B1.w - B0.w) * invc);

            float w = MIN_W_F * exp2f(wmod * LOG2_400_F);
            float q = 0.1f * exp2f(qmod * LOG2_20_F);
            float sh, ch;
            __sincosf(0.5f * w, &sh, &ch);
            float omc = 2.f * sh * sh;      // 1 - cos(w)
            float cw = 1.f - omc;
            float sw = 2.f * sh * ch;
            float alpha = __fdividef(sw, 2.f * q);
            float inva0 = __fdividef(1.f, 1.f + alpha);
            float b0 = 0.5f * omc * inva0;
            float b1c = omc * inva0;
            float a1 = -2.f * cw * inva0;
            float a2 = (1.f - alpha) * inva0;

            g_segA[r2] = make_float4(-a1, -a2, b1c - a1 * b0, b0 - a2 * b0);
            g_segB[r2] = make_float2(b0, mu);
        }
    }
}

// =====================================================================
// helpers for the scan kernels
// =====================================================================
__device__ __forceinline__ void unpack_ids(uint4 sv, int ids[SPT]) {
    ids[0] = sv.x & 0xffff; ids[1] = sv.x >> 16;
    ids[2] = sv.y & 0xffff; ids[3] = sv.y >> 16;
    ids[4] = sv.z & 0xffff; ids[5] = sv.z >> 16;
    ids[6] = sv.w & 0xffff; ids[7] = sv.w >> 16;
}

__device__ __forceinline__ void compose_regs(const float4 m[SPT],
        float& A00, float& A01, float& A10, float& A11, float& c1, float& c2) {
    A00 = 1.f; A01 = 0.f; A10 = 0.f; A11 = 1.f; c1 = 0.f; c2 = 0.f;
#pragma unroll
    for (int i = 0; i < SPT; i++) {
        float n00 = fmaf(m[i].x, A00, A10);
        float n01 = fmaf(m[i].x, A01, A11);
        float n10 = m[i].y * A00;
        float n11 = m[i].y * A01;
        float t1  = fmaf(m[i].x, c1, c2) + m[i].z;
        float t2  = fmaf(m[i].y, c1, m[i].w);
        A00 = n00; A01 = n01; A10 = n10; A11 = n11; c1 = t1; c2 = t2;
    }
}

// =====================================================================
// K4: smem-staged comb + per-chunk transform; writes xc and chunk aggs
// =====================================================================
__global__ void __launch_bounds__(BTH) k_scanA(const float* __restrict__ f0) {
    __shared__ float sxd[LAG + CHUNKN];   // 9216 B
    __shared__ float s00[BTH], s01[BTH], s10[BTH], s11[BTH], sc1[BTH], sc2[BTH];

    int tid = threadIdx.x, blk = blockIdx.x;
    int base = blk * CHUNKN;
    int row = base >> 16;
    int t0 = base & (Tn - 1);
    int rowoff = row * SEGCAP;

    // stage xd window [base-LAG, base+CHUNKN), zero-filled before row start
#pragma unroll
    for (int k = tid; k < (LAG + CHUNKN) / 4; k += BTH) {
        int off = k << 2;
        float4 v = make_float4(0.f, 0.f, 0.f, 0.f);
        if (t0 + off >= LAG) v = *(const float4*)&g_xd[base - LAG + off];
        *(float4*)&sxd[off] = v;
    }
    __syncthreads();

    int lbase = tid * SPT;
    int gbase = base + lbase;
    int ids[SPT];
    unpack_ids(*(const uint4*)&g_segids[gbase], ids);
    bool uni = (ids[0] == ids[SPT - 1]);
    float4 A = g_segA[rowoff + ids[0]];
    float2 Bc = g_segB[rowoff + ids[0]];

    float4 f0a = *(const float4*)&f0[gbase];
    float4 f0b = *(const float4*)&f0[gbase + 4];
    float f0v[SPT] = { f0a.x, f0a.y, f0a.z, f0a.w, f0b.x, f0b.y, f0b.z, f0b.w };

    float4 m[SPT];
    float xc[SPT];
#pragma unroll
    for (int i = 0; i < SPT; i++) {
        if (!uni && i) { A = g_segA[rowoff + ids[i]]; Bc = g_segB[rowoff + ids[i]]; }
        float p = f0v[i] * Bc.y;
        float z = floorf(p);
        float alfa = p - z;
        int zi = (int)z;
        int li = lbase + i + LAG;
        float x1 = sxd[li - zi - 1];
        float x2 = sxd[li - zi - 2];
        float v = sxd[li] - (1.f - alfa) * x1 - alfa * x2;
        xc[i] = v;
        m[i] = make_float4(A.x, A.y, A.z * v, A.w * v);
    }
    // write xc (two float4)
    *(float4*)&g_xc[gbase]     = make_float4(xc[0], xc[1], xc[2], xc[3]);
    *(float4*)&g_xc[gbase + 4] = make_float4(xc[4], xc[5], xc[6], xc[7]);

    float A00, A01, A10, A11, c1, c2;
    compose_regs(m, A00, A01, A10, A11, c1, c2);

    s00[tid] = A00; s01[tid] = A01; s10[tid] = A10; s11[tid] = A11;
    sc1[tid] = c1;  sc2[tid] = c2;
    for (int st = 1; st < BTH; st <<= 1) {
        __syncthreads();
        if ((tid & (2 * st - 1)) == 0) {
            int j = tid + st;
            float N00, N01, N10, N11, Nc1, Nc2;
            COMPOSE(s00[tid],s01[tid],s10[tid],s11[tid],sc1[tid],sc2[tid],
                    s00[j],  s01[j],  s10[j],  s11[j],  sc1[j],  sc2[j],
                    N00,N01,N10,N11,Nc1,Nc2);
            s00[tid] = N00; s01[tid] = N01; s10[tid] = N10; s11[tid] = N11;
            sc1[tid] = Nc1; sc2[tid] = Nc2;
        }
    }
    __syncthreads();
    if (tid == 0) {
        g_chunkM[blk] = make_float4(s00[0], s01[0], s10[0], s11[0]);
        g_chunkC[blk] = make_float2(sc1[0], sc2[0]);
    }
}

// =====================================================================
// K5: replay from xc — block KS scan + warp-0 incoming state + output
// =====================================================================
__global__ void __launch_bounds__(BTH) k_replay(float* __restrict__ out) {
    int tid = threadIdx.x, lane = tid & 31, wid = tid >> 5;
    int blk = blockIdx.x;
    int base = blk * CHUNKN;
    int row = base >> 16;
    int rowoff = row * SEGCAP;
    int gbase = base + tid * SPT;

    int ids[SPT];
    unpack_ids(*(const uint4*)&g_segids[gbase], ids);
    bool uni = (ids[0] == ids[SPT - 1]);
    float4 A = g_segA[rowoff + ids[0]];
    float2 Bc = g_segB[rowoff + ids[0]];

    float4 xa = *(const float4*)&g_xc[gbase];
    float4 xb = *(const float4*)&g_xc[gbase + 4];
    float xc[SPT] = { xa.x, xa.y, xa.z, xa.w, xb.x, xb.y, xb.z, xb.w };
    float4 m[SPT];
    float b0v[SPT];
#pragma unroll
    for (int i = 0; i < SPT; i++) {
        if (!uni && i) { A = g_segA[rowoff + ids[i]]; Bc = g_segB[rowoff + ids[i]]; }
        m[i] = make_float4(A.x, A.y, A.z * xc[i], A.w * xc[i]);
        b0v[i] = Bc.x;
    }
    float r00, r01, r10, r11, rc1, rc2;
    compose_regs(m, r00, r01, r10, r11, rc1, rc2);

    __shared__ float s00[BTH], s01[BTH], s10[BTH], s11[BTH], sc1[BTH], sc2[BTH];
    __shared__ float2 s_cin;

    // warp 0: incoming state from predecessor chunk aggregates (same row)
    if (wid == 0) {
        int chunk = blk & (NCHUNK - 1);
        int rowBlk = blk - chunk;
        float T00 = 1.f, T01 = 0.f, T10 = 0.f, T11 = 1.f, Tc1 = 0.f, Tc2 = 0.f;
        if (lane < chunk) {
            float4 M = g_chunkM[rowBlk + lane];
            float2 C = g_chunkC[rowBlk + lane];
            T00 = M.x; T01 = M.y; T10 = M.z; T11 = M.w; Tc1 = C.x; Tc2 = C.y;
        }
#pragma unroll
        for (int off = 1; off < 32; off <<= 1) {
            float E00 = __shfl_up_sync(~0u, T00, off);
            float E01 = __shfl_up_sync(~0u, T01, off);
            float E10 = __shfl_up_sync(~0u, T10, off);
            float E11 = __shfl_up_sync(~0u, T11, off);
            float Ec1 = __shfl_up_sync(~0u, Tc1, off);
            float Ec2 = __shfl_up_sync(~0u, Tc2, off);
            if (lane >= off) {
                float N00, N01, N10, N11, Nc1, Nc2;
                COMPOSE(E00,E01,E10,E11,Ec1,Ec2, T00,T01,T10,T11,Tc1,Tc2,
                        N00,N01,N10,N11,Nc1,Nc2);
                T00 = N00; T01 = N01; T10 = N10; T11 = N11; Tc1 = Nc1; Tc2 = Nc2;
            }
        }
        float i1 = 0.f, i2 = 0.f;
        if (chunk > 0) {
            i1 = __shfl_sync(~0u, Tc1, chunk - 1);
            i2 = __shfl_sync(~0u, Tc2, chunk - 1);
        }
        if (lane == 0) s_cin = make_float2(i1, i2);
    }

    s00[tid] = r00; s01[tid] = r01; s10[tid] = r10; s11[tid] = r11;
    sc1[tid] = rc1; sc2[tid] = rc2;
    __syncthreads();
    for (int st = 1; st < BTH; st <<= 1) {
        float E00 = 0.f, E01 = 0.f, E10 = 0.f, E11 = 0.f, Ec1 = 0.f, Ec2 = 0.f;
        bool has = (tid >= st);
        if (has) {
            E00 = s00[tid - st]; E01 = s01[tid - st];
            E10 = s10[tid - st]; E11 = s11[tid - st];
            Ec1 = sc1[tid - st]; Ec2 = sc2[tid - st];
        }
        __syncthreads();
        if (has) {
            float N00, N01, N10, N11, Nc1, Nc2;
            COMPOSE(E00,E01,E10,E11,Ec1,Ec2, r00,r01,r10,r11,rc1,rc2,
                    N00,N01,N10,N11,Nc1,Nc2);
            r00 = N00; r01 = N01; r10 = N10; r11 = N11; rc1 = Nc1; rc2 = Nc2;
            s00[tid] = r00; s01[tid] = r01; s10[tid] = r10; s11[tid] = r11;
            sc1[tid] = rc1; sc2[tid] = rc2;
        }
        __syncthreads();
    }
    float P00 = 1.f, P01 = 0.f, P10 = 0.f, P11 = 1.f, pc1 = 0.f, pc2 = 0.f;
    if (tid > 0) {
        P00 = s00[tid - 1]; P01 = s01[tid - 1];
        P10 = s10[tid - 1]; P11 = s11[tid - 1];
        pc1 = sc1[tid - 1]; pc2 = sc2[tid - 1];
    }
    float2 cin = s_cin;
    float st1 = fmaf(P00, cin.x, fmaf(P01, cin.y, pc1));
    float st2 = fmaf(P10, cin.x, fmaf(P11, cin.y, pc2));

    float ov[SPT];
#pragma unroll
    for (int i = 0; i < SPT; i++) {
        ov[i] = fmaf(b0v[i], xc[i], st1);
        float n1 = fmaf(m[i].x, st1, st2) + m[i].z;
        float n2 = fmaf(m[i].y, st1, m[i].w);
        st1 = n1; st2 = n2;
    }
    *(float4*)&out[gbase]     = make_float4(ov[0], ov[1], ov[2], ov[3]);
    *(float4*)&out[gbase + 4] = make_float4(ov[4], ov[5], ov[6], ov[7]);
}

// =====================================================================
extern "C" void kernel_launch(void* const* d_in, const int* in_sizes, int n_in,
                              void* d_out, int out_size) {
    const float* f0     = (const float*)d_in[0];
    const float* x      = (const float*)d_in[1];
    const float* params = (const float*)d_in[2];
    const int*   onsets = (const int*)d_in[3];
    float* out = (float*)d_out;

    k_tile<<<Bn * NT, 256>>>(onsets, (const float4*)params);
    k_ids<<<Bn * NT, 256>>>(onsets, (const float4*)params);
    k_xd<<<(Bn * Tn / 4) / 256, 256>>>((const float4*)x);
    k_scanA<<<Bn * NCHUNK, BTH>>>(f0);
    k_replay<<<Bn * NCHUNK, BTH>>>(out);
}

// round 8
// speedup vs baseline: 2.4758x; 1.1356x over previous
#include <cuda_runtime.h>

#define Bn 32
#define Tn 65536
#define TILE 2048
#define NT 32              /* tiles per row */
#define SEGCAP (Tn + 2)
#define NCHUNK 32
#define BTH 256
#define SPT 8              /* samples per thread in scan kernels */
#define LAG 256            /* staged history for comb (max lag ~202) */
#define CHUNKN (BTH * SPT) /* 2048 samples per scan block */
#define SWSZ ((LAG + CHUNKN) + ((LAG + CHUNKN) >> 5) + 4)

// ---------------- scratch (device globals) ----------------
static __device__ int    g_tO[Bn * NT];
static __device__ float4 g_tP[Bn * NT];
static __device__ int    g_nOn[Bn];
static __device__ unsigned short g_segids[Bn * Tn];  // 4 MB
static __device__ int    g_S[Bn * SEGCAP];
static __device__ float4 g_Bnd[Bn * SEGCAP];
static __device__ float4 g_segA[Bn * SEGCAP];        // m00, m10, v1, v2
static __device__ float2 g_segB[Bn * SEGCAP];        // b0, mu
static __device__ float  g_xd[Bn * Tn];              // 8 MB
static __device__ float  g_xc[Bn * Tn];              // 8 MB (comb output)
static __device__ float4 g_chunkM[Bn * NCHUNK];
static __device__ float2 g_chunkC[Bn * NCHUNK];

#define MIN_W_F     0.007853981633974483f
#define LOG2_400_F  8.643856189774724f
#define LOG2_20_F   4.321928094887363f

__device__ __forceinline__ float fast_sigmoid(float v) {
    return __fdividef(1.0f, 1.0f + __expf(-v));
}
__device__ __forceinline__ int SW(int j) { return j + (j >> 5); }

// N = L after E  (2x2 affine compose)
#define COMPOSE(E00,E01,E10,E11,Ec1,Ec2, L00,L01,L10,L11,Lc1,Lc2, \
                N00,N01,N10,N11,Nc1,Nc2)                          \
    do {                                                          \
        N00 = fmaf(L00, E00, L01 * E10);                          \
        N01 = fmaf(L00, E01, L01 * E11);                          \
        N10 = fmaf(L10, E00, L11 * E10);                          \
        N11 = fmaf(L10, E01, L11 * E11);                          \
        Nc1 = fmaf(L00, Ec1, fmaf(L01, Ec2, Lc1));                \
        Nc2 = fmaf(L10, Ec1, fmaf(L11, Ec2, Lc2));                \
    } while (0)

// =====================================================================
// K1: per-tile totals (coalesced, vectorized)
// =====================================================================
__global__ void __launch_bounds__(256) k_tile(const int4* __restrict__ onsets4,
                                              const float4* __restrict__ params) {
    int blk = blockIdx.x;
    int row = blk >> 5, tile = blk & (NT - 1);
    long base = (long)row * Tn + (long)tile * TILE;
    int tid = threadIdx.x;

    int o = 0;
    float4 ps = make_float4(0.f, 0.f, 0.f, 0.f);
#pragma unroll
    for (int k = 0; k < 2; k++) {
        int4 v = onsets4[(base >> 2) + k * 256 + tid];
        o += v.x + v.y + v.z + v.w;
    }
#pragma unroll
    for (int r = 0; r < 8; r++) {
        float4 p = params[base + r * 256 + tid];
        ps.x += p.x; ps.y += p.y; ps.z += p.z; ps.w += p.w;
    }
#pragma unroll
    for (int off = 16; off; off >>= 1) {
        o    += __shfl_down_sync(~0u, o, off);
        ps.x += __shfl_down_sync(~0u, ps.x, off);
        ps.y += __shfl_down_sync(~0u, ps.y, off);
        ps.z += __shfl_down_sync(~0u, ps.z, off);
        ps.w += __shfl_down_sync(~0u, ps.w, off);
    }
    __shared__ int    so[8];
    __shared__ float4 sp[8];
    int lane = tid & 31, wid = tid >> 5;
    if (lane == 0) { so[wid] = o; sp[wid] = ps; }
    __syncthreads();
    if (tid == 0) {
        int ot = 0; float4 pt = make_float4(0.f, 0.f, 0.f, 0.f);
#pragma unroll
        for (int w = 0; w < 8; w++) {
            ot += so[w];
            pt.x += sp[w].x; pt.y += sp[w].y; pt.z += sp[w].z; pt.w += sp[w].w;
        }
        g_tO[blk] = ot;
        g_tP[blk] = pt;
    }
}

// =====================================================================
// K2: segids + boundary scatter. Thread-sequential (8 samples) + one
//     warp shfl scan + one block combine. Tile carry from K1 aggregates.
// =====================================================================
__global__ void __launch_bounds__(256) k_ids(const int4* __restrict__ onsets4,
                                             const float4* __restrict__ params) {
    int blk = blockIdx.x;
    int row = blk >> 5, tile = blk & (NT - 1);
    long rowbase = (long)row * Tn;
    long base = rowbase + (long)tile * TILE;
    int tid = threadIdx.x, lane = tid & 31, wid = tid >> 5;
    int rowoff = row * SEGCAP;

    __shared__ int    waggO[8];
    __shared__ float4 waggP[8];
    __shared__ int    s_carO;
    __shared__ float4 s_carP;

    // warp 0: tile carry = sum of predecessor tile aggregates
    if (wid == 0) {
        int co = 0;
        float4 cp = make_float4(0.f, 0.f, 0.f, 0.f);
        if (lane < tile) {
            int pb = (row << 5) + lane;
            co = g_tO[pb];
            cp = g_tP[pb];
        }
#pragma unroll
        for (int off = 16; off; off >>= 1) {
            co   += __shfl_down_sync(~0u, co, off);
            cp.x += __shfl_down_sync(~0u, cp.x, off);
            cp.y += __shfl_down_sync(~0u, cp.y, off);
            cp.z += __shfl_down_sync(~0u, cp.z, off);
            cp.w += __shfl_down_sync(~0u, cp.w, off);
        }
        if (lane == 0) { s_carO = co; s_carP = cp; }
    }

    // thread-local loads: 8 consecutive samples
    long ebase = base + (long)tid * SPT;
    int4 oa = onsets4[ebase >> 2];
    int4 ob = onsets4[(ebase >> 2) + 1];
    int ol[SPT] = { oa.x, oa.y, oa.z, oa.w, ob.x, ob.y, ob.z, ob.w };
    float4 pl[SPT];
#pragma unroll
    for (int i = 0; i < SPT; i++) pl[i] = params[ebase + i];

    int totO = 0;
    float4 totP = make_float4(0.f, 0.f, 0.f, 0.f);
#pragma unroll
    for (int i = 0; i < SPT; i++) {
        totO += ol[i];
        totP.x += pl[i].x; totP.y += pl[i].y; totP.z += pl[i].z; totP.w += pl[i].w;
    }

    // warp inclusive scan of thread totals
    int inO = totO;
    float4 inP = totP;
#pragma unroll
    for (int off = 1; off < 32; off <<= 1) {
        int   eo = __shfl_up_sync(~0u, inO, off);
        float a = __shfl_up_sync(~0u, inP.x, off);
        float b = __shfl_up_sync(~0u, inP.y, off);
        float c = __shfl_up_sync(~0u, inP.z, off);
        float d = __shfl_up_sync(~0u, inP.w, off);
        if (lane >= off) { inO += eo; inP.x += a; inP.y += b; inP.z += c; inP.w += d; }
    }
    // lane-exclusive
    int exO = __shfl_up_sync(~0u, inO, 1);
    float4 exP;
    exP.x = __shfl_up_sync(~0u, inP.x, 1);
    exP.y = __shfl_up_sync(~0u, inP.y, 1);
    exP.z = __shfl_up_sync(~0u, inP.z, 1);
    exP.w = __shfl_up_sync(~0u, inP.w, 1);
    if (lane == 0) { exO = 0; exP = make_float4(0.f, 0.f, 0.f, 0.f); }
    if (lane == 31) { waggO[wid] = inO; waggP[wid] = inP; }
    __syncthreads();

    // warp-exclusive (sum lower warp aggregates, fixed order)
    int weO = 0;
    float4 weP = make_float4(0.f, 0.f, 0.f, 0.f);
#pragma unroll
    for (int w = 0; w < 8; w++) {
        if (w < wid) {
            weO += waggO[w];
            weP.x += waggP[w].x; weP.y += waggP[w].y;
            weP.z += waggP[w].z; weP.w += waggP[w].w;
        }
    }

    int carO = s_carO;
    float4 carP = s_carP;
    if (tid == 0 && tile == 0) {
        g_S[rowoff] = 0;
        g_Bnd[rowoff] = make_float4(0.f, 0.f, 0.f, 0.f);
    }

    int id = carO + weO + exO;
    float4 pex = make_float4(carP.x + weP.x + exP.x, carP.y + weP.y + exP.y,
                             carP.z + weP.z + exP.z, carP.w + weP.w + exP.w);
#pragma unroll
    for (int i = 0; i < SPT; i++) {
        id += ol[i];
        g_segids[ebase + i] = (unsigned short)id;
        if (ol[i]) {
            g_S[rowoff + id] = (int)(ebase + i - rowbase);
            g_Bnd[rowoff + id] = pex;
        }
        pex.x += pl[i].x; pex.y += pl[i].y; pex.z += pl[i].z; pex.w += pl[i].w;
    }

    // last thread of tile 31 holds row totals
    if (tid == 255 && tile == NT - 1) {
        g_nOn[row] = id;
        g_S[rowoff + id + 1]   = Tn;
        g_Bnd[rowoff + id + 1] = pex;
    }
}

// =====================================================================
// K3: xd = x * dist (4/thread, vectorized); blocks 0..Bn-1 also build
//     per-segment coefficient tables.
// =====================================================================
__global__ void __launch_bounds__(256) k_xd(const float4* __restrict__ x4) {
    int v = blockIdx.x * 256 + threadIdx.x;
    int idx = v << 2;
    int row = idx >> 16;
    int rowoff = row * SEGCAP;
    uint2 sv = *(const uint2*)&g_segids[idx];
    int id0 = sv.x & 0xffff, id3 = sv.y >> 16;
    float4 xv = x4[v];
    float4 ov;
    if (id0 == id3) {
        int ro = rowoff + id0;
        float num = g_Bnd[ro + 1].x - g_Bnd[ro].x;
        float den = (float)(g_S[ro + 1] - g_S[ro]);
        float a = num * __fdividef(1.f, fmaxf(den, 1.f));
        float dist = 0.1f * exp2f(fast_sigmoid(a) * LOG2_20_F);
        ov = make_float4(xv.x * dist, xv.y * dist, xv.z * dist, xv.w * dist);
    } else {
        int ids[4] = { (int)(sv.x & 0xffff), (int)(sv.x >> 16),
                       (int)(sv.y & 0xffff), (int)(sv.y >> 16) };
        float* o = &ov.x;
        const float* xi = &xv.x;
#pragma unroll
        for (int i = 0; i < 4; i++) {
            int ro = rowoff + ids[i];
            float num = g_Bnd[ro + 1].x - g_Bnd[ro].x;
            float den = (float)(g_S[ro + 1] - g_S[ro]);
            float a = num * __fdividef(1.f, fmaxf(den, 1.f));
            o[i] = xi[i] * (0.1f * exp2f(fast_sigmoid(a) * LOG2_20_F));
        }
    }
    *(float4*)&g_xd[idx] = ov;

    if (blockIdx.x < Bn) {
        int srow = blockIdx.x;
        int ro0 = srow * SEGCAP;
        int nOn = g_nOn[srow];
        for (int s = threadIdx.x; s <= nOn; s += 256) {
            int r2 = ro0 + s;
            float4 B0 = g_Bnd[r2], B1 = g_Bnd[r2 + 1];
            float d2 = (float)(g_S[r2 + 1] - g_S[r2]);
            float invc = __fdividef(1.f, fmaxf(d2, 1.f));
            float wmod = fast_sigmoid((B1.y - B0.y) * invc);
            float qmod = fast_sigmoid((B1.z - B0.z) * invc);
            float mu   = fast_sigmoid((B1.w - B0.w) * invc);

            float w = MIN_W_F * exp2f(wmod * LOG2_400_F);
            float q = 0.1f * exp2f(qmod * LOG2_20_F);
            float sh, ch;
            __sincosf(0.5f * w, &sh, &ch);
            float omc = 2.f * sh * sh;
            float cw = 1.f - omc;
            float sw = 2.f * sh * ch;
            float alpha = __fdividef(sw, 2.f * q);
            float inva0 = __fdividef(1.f, 1.f + alpha);
            float b0 = 0.5f * omc * inva0;
            float b1c = omc * inva0;
            float a1 = -2.f * cw * inva0;
            float a2 = (1.f - alpha) * inva0;

            g_segA[r2] = make_float4(-a1, -a2, b1c - a1 * b0, b0 - a2 * b0);
            g_segB[r2] = make_float2(b0, mu);
        }
    }
}

// =====================================================================
// helpers
// =====================================================================
__device__ __forceinline__ void unpack_ids(uint4 sv, int ids[SPT]) {
    ids[0] = sv.x & 0xffff; ids[1] = sv.x >> 16;
    ids[2] = sv.y & 0xffff; ids[3] = sv.y >> 16;
    ids[4] = sv.z & 0xffff; ids[5] = sv.z >> 16;
    ids[6] = sv.w & 0xffff; ids[7] = sv.w >> 16;
}

// thread-sequential compose of SPT steps built from (table, xc)
__device__ __forceinline__ void compose_thread(const int ids[SPT], bool uni,
        int rowoff, float4 T0, const float xc[SPT],
        float& A00, float& A01, float& A10, float& A11, float& c1, float& c2) {
    float4 T = T0;
    A00 = 1.f; A01 = 0.f; A10 = 0.f; A11 = 1.f; c1 = 0.f; c2 = 0.f;
#pragma unroll
    for (int i = 0; i < SPT; i++) {
        if (!uni && i) T = g_segA[rowoff + ids[i]];
        float n00 = fmaf(T.x, A00, A10);
        float n01 = fmaf(T.x, A01, A11);
        float n10 = T.y * A00;
        float n11 = T.y * A01;
        float t1  = fmaf(T.x, c1, c2) + T.z * xc[i];
        float t2  = fmaf(T.y, c1, T.w * xc[i]);
        A00 = n00; A01 = n01; A10 = n10; A11 = n11; c1 = t1; c2 = t2;
    }
}

// =====================================================================
// K4: smem-staged (swizzled) comb + chunk aggregate (all-shfl reduce)
// =====================================================================
__global__ void __launch_bounds__(BTH) k_scanA(const float* __restrict__ f0) {
    __shared__ float sxd[SWSZ];
    __shared__ float wagg[8][6];

    int tid = threadIdx.x, blk = blockIdx.x;
    int lane = tid & 31, wid = tid >> 5;
    int base = blk * CHUNKN;
    int t0 = base & (Tn - 1);
    int rowoff = (base >> 16) * SEGCAP;

    // stage xd window [base-LAG, base+CHUNKN): float4 gmem load,
    // 4 scalar swizzled smem stores (conflict-free by bank math)
#pragma unroll
    for (int k = tid; k < (LAG + CHUNKN) / 4; k += BTH) {
        int off = k << 2;
        float4 v = make_float4(0.f, 0.f, 0.f, 0.f);
        if (t0 + off >= LAG) v = *(const float4*)&g_xd[base - LAG + off];
        sxd[SW(off)]     = v.x;
        sxd[SW(off + 1)] = v.y;
        sxd[SW(off + 2)] = v.z;
        sxd[SW(off + 3)] = v.w;
    }
    __syncthreads();

    int lbase = tid * SPT;
    int gbase = base + lbase;
    int ids[SPT];
    unpack_ids(*(const uint4*)&g_segids[gbase], ids);
    bool uni = (ids[0] == ids[SPT - 1]);
    float4 T = g_segA[rowoff + ids[0]];
    float2 Bc = g_segB[rowoff + ids[0]];

    float4 f0a = *(const float4*)&f0[gbase];
    float4 f0b = *(const float4*)&f0[gbase + 4];
    float f0v[SPT] = { f0a.x, f0a.y, f0a.z, f0a.w, f0b.x, f0b.y, f0b.z, f0b.w };

    float xc[SPT];
#pragma unroll
    for (int i = 0; i < SPT; i++) {
        if (!uni && i) Bc = g_segB[rowoff + ids[i]];
        float p = f0v[i] * Bc.y;
        float z = floorf(p);
        float alfa = p - z;
        int zi = (int)z;
        int li = lbase + i + LAG;
        float x1 = sxd[SW(li - zi - 1)];
        float x2 = sxd[SW(li - zi - 2)];
        xc[i] = sxd[SW(li)] - (1.f - alfa) * x1 - alfa * x2;
    }
    *(float4*)&g_xc[gbase]     = make_float4(xc[0], xc[1], xc[2], xc[3]);
    *(float4*)&g_xc[gbase + 4] = make_float4(xc[4], xc[5], xc[6], xc[7]);

    float A00, A01, A10, A11, c1, c2;
    compose_thread(ids, uni, rowoff, T, xc, A00, A01, A10, A11, c1, c2);

    // warp ordered tree reduce (lane 0 ends with compose of lanes 0..31)
#pragma unroll
    for (int off = 1; off < 32; off <<= 1) {
        float L00 = __shfl_down_sync(~0u, A00, off);
        float L01 = __shfl_down_sync(~0u, A01, off);
        float L10 = __shfl_down_sync(~0u, A10, off);
        float L11 = __shfl_down_sync(~0u, A11, off);
        float Lc1 = __shfl_down_sync(~0u, c1, off);
        float Lc2 = __shfl_down_sync(~0u, c2, off);
        float N00, N01, N10, N11, Nc1, Nc2;
        COMPOSE(A00,A01,A10,A11,c1,c2, L00,L01,L10,L11,Lc1,Lc2,
                N00,N01,N10,N11,Nc1,Nc2);
        A00 = N00; A01 = N01; A10 = N10; A11 = N11; c1 = Nc1; c2 = Nc2;
    }
    if (lane == 0) {
        wagg[wid][0] = A00; wagg[wid][1] = A01; wagg[wid][2] = A10;
        wagg[wid][3] = A11; wagg[wid][4] = c1;  wagg[wid][5] = c2;
    }
    __syncthreads();
    if (wid == 0 && lane < 8) {
        float W00 = wagg[lane][0], W01 = wagg[lane][1], W10 = wagg[lane][2];
        float W11 = wagg[lane][3], Wc1 = wagg[lane][4], Wc2 = wagg[lane][5];
#pragma unroll
        for (int off = 1; off < 8; off <<= 1) {
            float L00 = __shfl_down_sync(0xffu, W00, off);
            float L01 = __shfl_down_sync(0xffu, W01, off);
            float L10 = __shfl_down_sync(0xffu, W10, off);
            float L11 = __shfl_down_sync(0xffu, W11, off);
            float Lc1 = __shfl_down_sync(0xffu, Wc1, off);
            float Lc2 = __shfl_down_sync(0xffu, Wc2, off);
            float N00, N01, N10, N11, Nc1, Nc2;
            COMPOSE(W00,W01,W10,W11,Wc1,Wc2, L00,L01,L10,L11,Lc1,Lc2,
                    N00,N01,N10,N11,Nc1,Nc2);
            W00 = N00; W01 = N01; W10 = N10; W11 = N11; Wc1 = Nc1; Wc2 = Nc2;
        }
        if (lane == 0) {
            g_chunkM[blk] = make_float4(W00, W01, W10, W11);
            g_chunkC[blk] = make_float2(Wc1, Wc2);
        }
    }
}

// =====================================================================
// K5: replay from xc — shfl scans only, one syncthreads
// =====================================================================
__global__ void __launch_bounds__(BTH) k_replay(float* __restrict__ out) {
    __shared__ float wagg[8][6];
    __shared__ float2 s_cin;

    int tid = threadIdx.x, lane = tid & 31, wid = tid >> 5;
    int blk = blockIdx.x;
    int base = blk * CHUNKN;
    int rowoff = (base >> 16) * SEGCAP;
    int gbase = base + tid * SPT;

    int ids[SPT];
    unpack_ids(*(const uint4*)&g_segids[gbase], ids);
    bool uni = (ids[0] == ids[SPT - 1]);
    float4 T0 = g_segA[rowoff + ids[0]];

    float4 xa = *(const float4*)&g_xc[gbase];
    float4 xb = *(const float4*)&g_xc[gbase + 4];
    float xc[SPT] = { xa.x, xa.y, xa.z, xa.w, xb.x, xb.y, xb.z, xb.w };

    float I00, I01, I10, I11, Ic1, Ic2;
    compose_thread(ids, uni, rowoff, T0, xc, I00, I01, I10, I11, Ic1, Ic2);

    // warp inclusive KS
#pragma unroll
    for (int off = 1; off < 32; off <<= 1) {
        float E00 = __shfl_up_sync(~0u, I00, off);
        float E01 = __shfl_up_sync(~0u, I01, off);
        float E10 = __shfl_up_sync(~0u, I10, off);
        float E11 = __shfl_up_sync(~0u, I11, off);
        float Ec1 = __shfl_up_sync(~0u, Ic1, off);
        float Ec2 = __shfl_up_sync(~0u, Ic2, off);
        if (lane >= off) {
            float N00, N01, N10, N11, Nc1, Nc2;
            COMPOSE(E00,E01,E10,E11,Ec1,Ec2, I00,I01,I10,I11,Ic1,Ic2,
                    N00,N01,N10,N11,Nc1,Nc2);
            I00 = N00; I01 = N01; I10 = N10; I11 = N11; Ic1 = Nc1; Ic2 = Nc2;
        }
    }
    // lane-exclusive
    float X00 = __shfl_up_sync(~0u, I00, 1);
    float X01 = __shfl_up_sync(~0u, I01, 1);
    float X10 = __shfl_up_sync(~0u, I10, 1);
    float X11 = __shfl_up_sync(~0u, I11, 1);
    float Xc1 = __shfl_up_sync(~0u, Ic1, 1);
    float Xc2 = __shfl_up_sync(~0u, Ic2, 1);
    if (lane == 0) { X00 = 1.f; X01 = 0.f; X10 = 0.f; X11 = 1.f; Xc1 = 0.f; Xc2 = 0.f; }
    if (lane == 31) {
        wagg[wid][0] = I00; wagg[wid][1] = I01; wagg[wid][2] = I10;
        wagg[wid][3] = I11; wagg[wid][4] = Ic1; wagg[wid][5] = Ic2;
    }

    // warp 0: incoming chunk state from predecessor aggregates
    if (wid == 0) {
        int chunk = blk & (NCHUNK - 1);
        int rowBlk = blk - chunk;
        float T00 = 1.f, T01 = 0.f, T10 = 0.f, T11 = 1.f, Tc1 = 0.f, Tc2 = 0.f;
        if (lane < chunk) {
            float4 M = g_chunkM[rowBlk + lane];
            float2 C = g_chunkC[rowBlk + lane];
            T00 = M.x; T01 = M.y; T10 = M.z; T11 = M.w; Tc1 = C.x; Tc2 = C.y;
        }
#pragma unroll
        for (int off = 1; off < 32; off <<= 1) {
            float E00 = __shfl_up_sync(~0u, T00, off);
            float E01 = __shfl_up_sync(~0u, T01, off);
            float E10 = __shfl_up_sync(~0u, T10, off);
            float E11 = __shfl_up_sync(~0u, T11, off);
            float Ec1 = __shfl_up_sync(~0u, Tc1, off);
            float Ec2 = __shfl_up_sync(~0u, Tc2, off);
            if (lane >= off) {
                float N00, N01, N10, N11, Nc1, Nc2;
                COMPOSE(E00,E01,E10,E11,Ec1,Ec2, T00,T01,T10,T11,Tc1,Tc2,
                        N00,N01,N10,N11,Nc1,Nc2);
                T00 = N00; T01 = N01; T10 = N10; T11 = N11; Tc1 = Nc1; Tc2 = Nc2;
            }
        }
        float i1 = 0.f, i2 = 0.f;
        if (chunk > 0) {
            i1 = __shfl_sync(~0u, Tc1, chunk - 1);
            i2 = __shfl_sync(~0u, Tc2, chunk - 1);
        }
        if (lane == 0) s_cin = make_float2(i1, i2);
    }
    __syncthreads();

    // incoming state: cin -> warp-exclusive -> lane-exclusive (apply to vec)
    float2 cin = s_cin;
    float s1 = cin.x, s2 = cin.y;
#pragma unroll
    for (int w = 0; w < 8; w++) {
        if (w < wid) {
            float n1 = fmaf(wagg[w][0], s1, fmaf(wagg[w][1], s2, wagg[w][4]));
            float n2 = fmaf(wagg[w][2], s1, fmaf(wagg[w][3], s2, wagg[w][5]));
            s1 = n1; s2 = n2;
        }
    }
    float st1 = fmaf(X00, s1, fmaf(X01, s2, Xc1));
    float st2 = fmaf(X10, s1, fmaf(X11, s2, Xc2));

    // replay
    float4 T = T0;
    float2 Bc = g_segB[rowoff + ids[0]];
    float ov[SPT];
#pragma unroll
    for (int i = 0; i < SPT; i++) {
        if (!uni && i) { T = g_segA[rowoff + ids[i]]; Bc = g_segB[rowoff + ids[i]]; }
        ov[i] = fmaf(Bc.x, xc[i], st1);
        float n1 = fmaf(T.x, st1, st2) + T.z * xc[i];
        float n2 = fmaf(T.y, st1, T.w * xc[i]);
        st1 = n1; st2 = n2;
    }
    *(float4*)&out[gbase]     = make_float4(ov[0], ov[1], ov[2], ov[3]);
    *(float4*)&out[gbase + 4] = make_float4(ov[4], ov[5], ov[6], ov[7]);
}

// =====================================================================
extern "C" void kernel_launch(void* const* d_in, const int* in_sizes, int n_in,
                              void* d_out, int out_size) {
    const float* f0     = (const float*)d_in[0];
    const float* x      = (const float*)d_in[1];
    const float* params = (const float*)d_in[2];
    const int*   onsets = (const int*)d_in[3];
    float* out = (float*)d_out;

    k_tile<<<Bn * NT, 256>>>((const int4*)onsets, (const float4*)params);
    k_ids<<<Bn * NT, 256>>>((const int4*)onsets, (const float4*)params);
    k_xd<<<(Bn * Tn / 4) / 256, 256>>>((const float4*)x);
    k_scanA<<<Bn * NCHUNK, BTH>>>(f0);
    k_replay<<<Bn * NCHUNK, BTH>>>(out);
}